// round 1
// baseline (speedup 1.0000x reference)
#include <cuda_runtime.h>

#define N_NODES 25000
#define E_EDGES 200000
#define DIN 512
#define HID 512

// Scratch (allocation-free: __device__ globals)
__device__ float g_bufA[N_NODES * HID];   // 51.2 MB
__device__ float g_bufB[N_NODES * HID];   // 51.2 MB
__device__ float g_deg[N_NODES];
__device__ float g_dis[N_NODES];

// ---------------------------------------------------------------------------
// Degree pipeline
// ---------------------------------------------------------------------------
__global__ void deg_init_kernel(float* deg) {
    int i = blockIdx.x * blockDim.x + threadIdx.x;
    if (i < N_NODES) deg[i] = 1.0f;   // self-loop
}

__global__ void deg_count_kernel(const int* __restrict__ dst, float* deg) {
    int e = blockIdx.x * blockDim.x + threadIdx.x;
    if (e < E_EDGES) atomicAdd(&deg[dst[e]], 1.0f);
}

__global__ void deg_rsqrt_kernel(const float* __restrict__ deg, float* dis) {
    int i = blockIdx.x * blockDim.x + threadIdx.x;
    if (i < N_NODES) dis[i] = rsqrtf(deg[i]);
}

// ---------------------------------------------------------------------------
// fp32 GEMM: C[M,512] = A[M,512] @ B[512,512]   (no bias; bias added later)
// BM=64, BN=64, BK=16, 256 threads, 4x4 per thread
// ---------------------------------------------------------------------------
__global__ __launch_bounds__(256)
void gemm_kernel(const float* __restrict__ A, const float* __restrict__ B,
                 float* __restrict__ C, int M) {
    __shared__ float As[16][64];
    __shared__ float Bs[16][64];

    int tid = threadIdx.x;
    int block_m = blockIdx.y * 64;
    int block_n = blockIdx.x * 64;
    int tx = tid & 15;       // 0..15 -> output cols tx*4..tx*4+3
    int ty = tid >> 4;       // 0..15 -> output rows ty*4..ty*4+3

    // A tile load: 64 rows x 16 k = 1024 floats = 256 float4
    int arow = tid >> 2;           // 0..63
    int ak4  = (tid & 3) * 4;      // 0,4,8,12
    // B tile load: 16 k x 64 cols
    int bk   = tid >> 4;           // 0..15
    int bc4  = (tid & 15) * 4;     // 0..60

    float acc[4][4] = {};

    for (int k0 = 0; k0 < 512; k0 += 16) {
        int gr = block_m + arow;
        float4 av;
        if (gr < M) av = *(const float4*)(A + (size_t)gr * 512 + k0 + ak4);
        else        av = make_float4(0.f, 0.f, 0.f, 0.f);
        As[ak4 + 0][arow] = av.x;
        As[ak4 + 1][arow] = av.y;
        As[ak4 + 2][arow] = av.z;
        As[ak4 + 3][arow] = av.w;

        float4 bv = *(const float4*)(B + (size_t)(k0 + bk) * 512 + block_n + bc4);
        *(float4*)&Bs[bk][bc4] = bv;

        __syncthreads();

        #pragma unroll
        for (int kk = 0; kk < 16; kk++) {
            float a[4], b[4];
            #pragma unroll
            for (int i = 0; i < 4; i++) a[i] = As[kk][ty * 4 + i];
            #pragma unroll
            for (int j = 0; j < 4; j++) b[j] = Bs[kk][tx * 4 + j];
            #pragma unroll
            for (int i = 0; i < 4; i++)
                #pragma unroll
                for (int j = 0; j < 4; j++)
                    acc[i][j] = fmaf(a[i], b[j], acc[i][j]);
        }
        __syncthreads();
    }

    #pragma unroll
    for (int i = 0; i < 4; i++) {
        int gr = block_m + ty * 4 + i;
        if (gr < M) {
            float4 o = make_float4(acc[i][0], acc[i][1], acc[i][2], acc[i][3]);
            *(float4*)(C + (size_t)gr * 512 + block_n + tx * 4) = o;
        }
    }
}

// ---------------------------------------------------------------------------
// agg[n,:] = hw[n,:] * dis[n]^2   (self-loop init; also zero-initializes agg)
// ---------------------------------------------------------------------------
__global__ void self_init_kernel(const float* __restrict__ hw,
                                 const float* __restrict__ dis,
                                 float* __restrict__ agg) {
    int idx4 = blockIdx.x * blockDim.x + threadIdx.x;  // over N*128 float4s
    if (idx4 >= N_NODES * 128) return;
    int node = idx4 >> 7;
    float d = dis[node];
    float dd = d * d;
    float4 v = ((const float4*)hw)[idx4];
    v.x *= dd; v.y *= dd; v.z *= dd; v.w *= dd;
    ((float4*)agg)[idx4] = v;
}

// ---------------------------------------------------------------------------
// Edge aggregation: one block of 128 threads per edge.
// agg[dst,:] += hw[src,:] * dis[src]*dis[dst]
// ---------------------------------------------------------------------------
__global__ __launch_bounds__(128)
void edge_agg_kernel(const float* __restrict__ hw,
                     const int* __restrict__ src,
                     const int* __restrict__ dst,
                     const float* __restrict__ dis,
                     float* __restrict__ agg) {
    int e = blockIdx.x;
    int s = __ldg(&src[e]);
    int d = __ldg(&dst[e]);
    float nrm = __ldg(&dis[s]) * __ldg(&dis[d]);

    const float4* hs = (const float4*)(hw + (size_t)s * 512);
    float* ad = agg + (size_t)d * 512;

    int i = threadIdx.x;              // 0..127, one float4 each
    float4 v = hs[i];
    int base = i * 4;
    atomicAdd(ad + base + 0, v.x * nrm);
    atomicAdd(ad + base + 1, v.y * nrm);
    atomicAdd(ad + base + 2, v.z * nrm);
    atomicAdd(ad + base + 3, v.w * nrm);
}

// ---------------------------------------------------------------------------
// h[n,c] = relu(agg[n,c] + b[c])
// ---------------------------------------------------------------------------
__global__ void bias_relu_kernel(const float* __restrict__ agg,
                                 const float* __restrict__ bias,
                                 float* __restrict__ h) {
    int idx4 = blockIdx.x * blockDim.x + threadIdx.x;  // over N*128 float4s
    if (idx4 >= N_NODES * 128) return;
    int c4 = (idx4 & 127) * 4;
    float4 v = ((const float4*)agg)[idx4];
    float4 b = *(const float4*)(bias + c4);
    v.x = fmaxf(v.x + b.x, 0.f);
    v.y = fmaxf(v.y + b.y, 0.f);
    v.z = fmaxf(v.z + b.z, 0.f);
    v.w = fmaxf(v.w + b.w, 0.f);
    ((float4*)h)[idx4] = v;
}

// ---------------------------------------------------------------------------
// Two-head output: out[n] = h2[n,:]·Wo + bo ; out[N+n] = h2[n,:]·Ww + bw
// One warp per node, 8 warps per block.
// ---------------------------------------------------------------------------
__global__ __launch_bounds__(256)
void heads_kernel(const float* __restrict__ h,
                  const float* __restrict__ Wo, const float* __restrict__ bo,
                  const float* __restrict__ Ww, const float* __restrict__ bw,
                  float* __restrict__ out) {
    __shared__ float swo[512];
    __shared__ float sww[512];
    int tid = threadIdx.x;
    for (int i = tid; i < 512; i += 256) {
        swo[i] = Wo[i];
        sww[i] = Ww[i];
    }
    __syncthreads();

    int warp = tid >> 5, lane = tid & 31;
    int node = blockIdx.x * 8 + warp;
    if (node >= N_NODES) return;

    const float* hr = h + (size_t)node * 512;
    float so = 0.f, sw = 0.f;
    #pragma unroll
    for (int j = 0; j < 16; j++) {
        int c = lane + j * 32;
        float v = hr[c];
        so = fmaf(v, swo[c], so);
        sw = fmaf(v, sww[c], sw);
    }
    #pragma unroll
    for (int off = 16; off; off >>= 1) {
        so += __shfl_down_sync(0xffffffff, so, off);
        sw += __shfl_down_sync(0xffffffff, sw, off);
    }
    if (lane == 0) {
        out[node]           = so + bo[0];
        out[N_NODES + node] = sw + bw[0];
    }
}

// ---------------------------------------------------------------------------
// Launch
// ---------------------------------------------------------------------------
extern "C" void kernel_launch(void* const* d_in, const int* in_sizes, int n_in,
                              void* d_out, int out_size) {
    const float* x  = (const float*)d_in[0];
    const int*   ei = (const int*)d_in[1];
    const float* W1 = (const float*)d_in[2];
    const float* b1 = (const float*)d_in[3];
    const float* W2 = (const float*)d_in[4];
    const float* b2 = (const float*)d_in[5];
    const float* Wo = (const float*)d_in[6];
    const float* bo = (const float*)d_in[7];
    const float* Ww = (const float*)d_in[8];
    const float* bw = (const float*)d_in[9];

    const int* src = ei;
    const int* dst = ei + E_EDGES;
    float* out = (float*)d_out;

    float *bufA, *bufB, *deg, *dis;
    cudaGetSymbolAddress((void**)&bufA, g_bufA);
    cudaGetSymbolAddress((void**)&bufB, g_bufB);
    cudaGetSymbolAddress((void**)&deg,  g_deg);
    cudaGetSymbolAddress((void**)&dis,  g_dis);

    const int NT = 256;
    int nb_nodes = (N_NODES + NT - 1) / NT;
    int nb_edges = (E_EDGES + NT - 1) / NT;
    int nb_elem4 = (N_NODES * 128 + NT - 1) / NT;

    // degree / norm
    deg_init_kernel<<<nb_nodes, NT>>>(deg);
    deg_count_kernel<<<nb_edges, NT>>>(dst, deg);
    deg_rsqrt_kernel<<<nb_nodes, NT>>>(deg, dis);

    dim3 ggrid(512 / 64, (N_NODES + 63) / 64);

    // Layer 1: hw1 = x @ W1 -> bufA ; agg -> bufB ; h1 = relu(bufB+b1) -> bufA
    gemm_kernel<<<ggrid, 256>>>(x, W1, bufA, N_NODES);
    self_init_kernel<<<nb_elem4, NT>>>(bufA, dis, bufB);
    edge_agg_kernel<<<E_EDGES, 128>>>(bufA, src, dst, dis, bufB);
    bias_relu_kernel<<<nb_elem4, NT>>>(bufB, b1, bufA);

    // Layer 2: hw2 = h1 @ W2 -> bufB ; agg -> bufA ; h2 = relu(bufA+b2) -> bufA
    gemm_kernel<<<ggrid, 256>>>(bufA, W2, bufB, N_NODES);
    self_init_kernel<<<nb_elem4, NT>>>(bufB, dis, bufA);
    edge_agg_kernel<<<E_EDGES, 128>>>(bufB, src, dst, dis, bufA);
    bias_relu_kernel<<<nb_elem4, NT>>>(bufA, b2, bufA);

    // Heads
    heads_kernel<<<(N_NODES + 7) / 8, 256>>>(bufA, Wo, bo, Ww, bw, out);
}

// round 3
// speedup vs baseline: 1.8189x; 1.8189x over previous
#include <cuda_runtime.h>
#include <cuda_bf16.h>
#include <mma.h>
#include <cstdint>

using namespace nvcuda;

#define N_NODES 25000
#define E_EDGES 200000
#define HID 512
#define MT 196
#define MPAD (MT * 128)        // 25088

// ---------------------------------------------------------------------------
// Scratch (allocation-free: __device__ globals)
// ---------------------------------------------------------------------------
__device__ float g_bufA[MPAD * HID];            // 51.4 MB
__device__ float g_bufB[MPAD * HID];            // 51.4 MB
__device__ float g_deg[N_NODES];
__device__ float g_dis[N_NODES];
__device__ __nv_bfloat16 g_Ah[MPAD * HID];      // 25.7 MB
__device__ __nv_bfloat16 g_Al[MPAD * HID];      // 25.7 MB
__device__ __nv_bfloat16 g_B1h[HID * HID];
__device__ __nv_bfloat16 g_B1l[HID * HID];
__device__ __nv_bfloat16 g_B2h[HID * HID];
__device__ __nv_bfloat16 g_B2l[HID * HID];

// ---------------------------------------------------------------------------
// Degree pipeline
// ---------------------------------------------------------------------------
__global__ void deg_init_kernel(float* deg) {
    int i = blockIdx.x * blockDim.x + threadIdx.x;
    if (i < N_NODES) deg[i] = 1.0f;
}
__global__ void deg_count_kernel(const int* __restrict__ dst, float* deg) {
    int e = blockIdx.x * blockDim.x + threadIdx.x;
    if (e < E_EDGES) atomicAdd(&deg[dst[e]], 1.0f);
}
__global__ void deg_rsqrt_kernel(const float* __restrict__ deg, float* dis) {
    int i = blockIdx.x * blockDim.x + threadIdx.x;
    if (i < N_NODES) dis[i] = rsqrtf(deg[i]);
}

// ---------------------------------------------------------------------------
// Pack activations [MPAD][512] fp32 -> bf16 hi/lo (row-major).
// mode 0: v = src[m,k] ; mode 1: v = relu(src[m,k] + bias[k])
// ---------------------------------------------------------------------------
__global__ __launch_bounds__(256)
void pack_act_kernel(const float* __restrict__ src, const float* __restrict__ bias,
                     __nv_bfloat16* __restrict__ outH, __nv_bfloat16* __restrict__ outL,
                     int mode) {
    int idx = blockIdx.x * blockDim.x + threadIdx.x;   // over MPAD*256 col-pairs
    if (idx >= MPAD * 256) return;
    int m = idx >> 8;
    int k = (idx & 255) * 2;

    float v0 = 0.f, v1 = 0.f;
    if (m < N_NODES) {
        float2 v = *(const float2*)(src + (size_t)m * HID + k);
        v0 = v.x; v1 = v.y;
        if (mode) {
            float2 b = *(const float2*)(bias + k);
            v0 = fmaxf(v0 + b.x, 0.f);
            v1 = fmaxf(v1 + b.y, 0.f);
        }
    }
    __nv_bfloat16 h0 = __float2bfloat16_rn(v0);
    __nv_bfloat16 h1 = __float2bfloat16_rn(v1);
    __nv_bfloat16 l0 = __float2bfloat16_rn(v0 - __bfloat162float(h0));
    __nv_bfloat16 l1 = __float2bfloat16_rn(v1 - __bfloat162float(h1));

    size_t off = (size_t)m * HID + k;
    *(__nv_bfloat162*)(outH + off) = __nv_bfloat162(h0, h1);
    *(__nv_bfloat162*)(outL + off) = __nv_bfloat162(l0, l1);
}

// ---------------------------------------------------------------------------
// Pack W[512,512] fp32 -> bf16 hi/lo, same [k][n] row-major layout.
// ---------------------------------------------------------------------------
__global__ __launch_bounds__(256)
void pack_w_kernel(const float* __restrict__ W,
                   __nv_bfloat16* __restrict__ outH, __nv_bfloat16* __restrict__ outL) {
    int idx = blockIdx.x * blockDim.x + threadIdx.x;   // 512*256 pairs
    if (idx >= 512 * 256) return;
    int k = idx >> 8;
    int n = (idx & 255) * 2;

    float2 v = *(const float2*)(W + (size_t)k * HID + n);
    __nv_bfloat16 h0 = __float2bfloat16_rn(v.x);
    __nv_bfloat16 h1 = __float2bfloat16_rn(v.y);
    __nv_bfloat16 l0 = __float2bfloat16_rn(v.x - __bfloat162float(h0));
    __nv_bfloat16 l1 = __float2bfloat16_rn(v.y - __bfloat162float(h1));

    size_t off = (size_t)k * HID + n;
    *(__nv_bfloat162*)(outH + off) = __nv_bfloat162(h0, h1);
    *(__nv_bfloat162*)(outL + off) = __nv_bfloat162(l0, l1);
}

// ---------------------------------------------------------------------------
// WMMA bf16-split GEMM: C[MPAD,512] = A[MPAD,512] @ B[512,512], fp32 out.
// Block 128x128, BK=32, 8 warps (4 along m x 2 along n), warp tile 32x64.
// acc += Ah*Bh + Al*Bh + Ah*Bl
// ---------------------------------------------------------------------------
__global__ __launch_bounds__(256)
void gemm_wmma_kernel(const __nv_bfloat16* __restrict__ Ah, const __nv_bfloat16* __restrict__ Al,
                      const __nv_bfloat16* __restrict__ Bh, const __nv_bfloat16* __restrict__ Bl,
                      float* __restrict__ C) {
    __shared__ __nv_bfloat16 Ash[128][40];
    __shared__ __nv_bfloat16 Asl[128][40];
    __shared__ __nv_bfloat16 Bsh[32][136];
    __shared__ __nv_bfloat16 Bsl[32][136];

    int tid = threadIdx.x;
    int bm = blockIdx.y * 128;
    int bn = blockIdx.x * 128;
    int wid = tid >> 5;
    int wm = (wid & 3) * 32;
    int wn = (wid >> 2) * 64;

    wmma::fragment<wmma::accumulator, 16, 16, 16, float> acc[2][4];
    #pragma unroll
    for (int i = 0; i < 2; i++)
        #pragma unroll
        for (int j = 0; j < 4; j++)
            wmma::fill_fragment(acc[i][j], 0.0f);

    int arow = tid >> 2;          // 0..63
    int acol = (tid & 3) * 8;     // 0,8,16,24
    int brow = tid >> 4;          // 0..15
    int bcol = (tid & 15) * 8;    // 0..120

    for (int k0 = 0; k0 < 512; k0 += 32) {
        #pragma unroll
        for (int r = 0; r < 2; r++) {
            int row = arow + r * 64;
            size_t g = (size_t)(bm + row) * HID + k0 + acol;
            *(uint4*)&Ash[row][acol] = *(const uint4*)(Ah + g);
            *(uint4*)&Asl[row][acol] = *(const uint4*)(Al + g);
        }
        #pragma unroll
        for (int r = 0; r < 2; r++) {
            int row = brow + r * 16;
            size_t g = (size_t)(k0 + row) * HID + bn + bcol;
            *(uint4*)&Bsh[row][bcol] = *(const uint4*)(Bh + g);
            *(uint4*)&Bsl[row][bcol] = *(const uint4*)(Bl + g);
        }
        __syncthreads();

        #pragma unroll
        for (int kk = 0; kk < 32; kk += 16) {
            wmma::fragment<wmma::matrix_a, 16, 16, 16, __nv_bfloat16, wmma::row_major> fa_h[2], fa_l[2];
            wmma::fragment<wmma::matrix_b, 16, 16, 16, __nv_bfloat16, wmma::row_major> fb_h[4], fb_l[4];
            #pragma unroll
            for (int i = 0; i < 2; i++) {
                wmma::load_matrix_sync(fa_h[i], &Ash[wm + i * 16][kk], 40);
                wmma::load_matrix_sync(fa_l[i], &Asl[wm + i * 16][kk], 40);
            }
            #pragma unroll
            for (int j = 0; j < 4; j++) {
                wmma::load_matrix_sync(fb_h[j], &Bsh[kk][wn + j * 16], 136);
                wmma::load_matrix_sync(fb_l[j], &Bsl[kk][wn + j * 16], 136);
            }
            #pragma unroll
            for (int i = 0; i < 2; i++)
                #pragma unroll
                for (int j = 0; j < 4; j++) {
                    wmma::mma_sync(acc[i][j], fa_h[i], fb_h[j], acc[i][j]);
                    wmma::mma_sync(acc[i][j], fa_l[i], fb_h[j], acc[i][j]);
                    wmma::mma_sync(acc[i][j], fa_h[i], fb_l[j], acc[i][j]);
                }
        }
        __syncthreads();
    }

    #pragma unroll
    for (int i = 0; i < 2; i++)
        #pragma unroll
        for (int j = 0; j < 4; j++)
            wmma::store_matrix_sync(C + (size_t)(bm + wm + i * 16) * HID + bn + wn + j * 16,
                                    acc[i][j], HID, wmma::mem_row_major);
}

// ---------------------------------------------------------------------------
// agg[n,:] = hw[n,:] * dis[n]^2
// ---------------------------------------------------------------------------
__global__ void self_init_kernel(const float* __restrict__ hw,
                                 const float* __restrict__ dis,
                                 float* __restrict__ agg) {
    int idx4 = blockIdx.x * blockDim.x + threadIdx.x;
    if (idx4 >= N_NODES * 128) return;
    int node = idx4 >> 7;
    float d = dis[node];
    float dd = d * d;
    float4 v = ((const float4*)hw)[idx4];
    v.x *= dd; v.y *= dd; v.z *= dd; v.w *= dd;
    ((float4*)agg)[idx4] = v;
}

// ---------------------------------------------------------------------------
// Edge aggregation: agg[dst,:] += hw[src,:] * dis[src]*dis[dst]
// One block of 128 threads per edge; one red.global.add.v4.f32 per thread.
// ---------------------------------------------------------------------------
__global__ __launch_bounds__(128)
void edge_agg_kernel(const float* __restrict__ hw,
                     const int* __restrict__ src,
                     const int* __restrict__ dst,
                     const float* __restrict__ dis,
                     float* __restrict__ agg) {
    int e = blockIdx.x;
    int s = __ldg(&src[e]);
    int d = __ldg(&dst[e]);
    float nrm = __ldg(&dis[s]) * __ldg(&dis[d]);

    const float4* hs = (const float4*)(hw + (size_t)s * HID);
    float* ad = agg + (size_t)d * HID;

    int i = threadIdx.x;
    float4 v = hs[i];
    asm volatile("red.global.add.v4.f32 [%0], {%1, %2, %3, %4};"
                 :: "l"(ad + i * 4), "f"(v.x * nrm), "f"(v.y * nrm),
                    "f"(v.z * nrm), "f"(v.w * nrm)
                 : "memory");
}

// ---------------------------------------------------------------------------
// Heads with fused bias+relu: h = relu(agg + b2); out = h·Wo+bo, h·Ww+bw
// ---------------------------------------------------------------------------
__global__ __launch_bounds__(256)
void heads_kernel(const float* __restrict__ agg, const float* __restrict__ b2,
                  const float* __restrict__ Wo, const float* __restrict__ bo,
                  const float* __restrict__ Ww, const float* __restrict__ bw,
                  float* __restrict__ out) {
    __shared__ float swo[512];
    __shared__ float sww[512];
    __shared__ float sb[512];
    int tid = threadIdx.x;
    for (int i = tid; i < 512; i += 256) {
        swo[i] = Wo[i];
        sww[i] = Ww[i];
        sb[i]  = b2[i];
    }
    __syncthreads();

    int warp = tid >> 5, lane = tid & 31;
    int node = blockIdx.x * 8 + warp;
    if (node >= N_NODES) return;

    const float* ar = agg + (size_t)node * HID;
    float so = 0.f, sw = 0.f;
    #pragma unroll
    for (int j = 0; j < 16; j++) {
        int c = lane + j * 32;
        float v = fmaxf(ar[c] + sb[c], 0.f);
        so = fmaf(v, swo[c], so);
        sw = fmaf(v, sww[c], sw);
    }
    #pragma unroll
    for (int off = 16; off; off >>= 1) {
        so += __shfl_down_sync(0xffffffff, so, off);
        sw += __shfl_down_sync(0xffffffff, sw, off);
    }
    if (lane == 0) {
        out[node]           = so + bo[0];
        out[N_NODES + node] = sw + bw[0];
    }
}

// ---------------------------------------------------------------------------
// Launch
// ---------------------------------------------------------------------------
extern "C" void kernel_launch(void* const* d_in, const int* in_sizes, int n_in,
                              void* d_out, int out_size) {
    const float* x  = (const float*)d_in[0];
    const int*   ei = (const int*)d_in[1];
    const float* W1 = (const float*)d_in[2];
    const float* b1 = (const float*)d_in[3];
    const float* W2 = (const float*)d_in[4];
    const float* b2 = (const float*)d_in[5];
    const float* Wo = (const float*)d_in[6];
    const float* bo = (const float*)d_in[7];
    const float* Ww = (const float*)d_in[8];
    const float* bw = (const float*)d_in[9];

    const int* src = ei;
    const int* dst = ei + E_EDGES;
    float* out = (float*)d_out;

    float *bufA, *bufB, *deg, *dis;
    __nv_bfloat16 *Ah, *Al, *B1h, *B1l, *B2h, *B2l;
    cudaGetSymbolAddress((void**)&bufA, g_bufA);
    cudaGetSymbolAddress((void**)&bufB, g_bufB);
    cudaGetSymbolAddress((void**)&deg,  g_deg);
    cudaGetSymbolAddress((void**)&dis,  g_dis);
    cudaGetSymbolAddress((void**)&Ah,   g_Ah);
    cudaGetSymbolAddress((void**)&Al,   g_Al);
    cudaGetSymbolAddress((void**)&B1h,  g_B1h);
    cudaGetSymbolAddress((void**)&B1l,  g_B1l);
    cudaGetSymbolAddress((void**)&B2h,  g_B2h);
    cudaGetSymbolAddress((void**)&B2l,  g_B2l);

    const int NT = 256;
    int nb_nodes = (N_NODES + NT - 1) / NT;
    int nb_edges = (E_EDGES + NT - 1) / NT;
    int nb_elem4 = (N_NODES * 128 + NT - 1) / NT;
    int nb_pack  = (MPAD * 256 + NT - 1) / NT;
    int nb_wpack = (512 * 256 + NT - 1) / NT;

    // degree / norm
    deg_init_kernel<<<nb_nodes, NT>>>(deg);
    deg_count_kernel<<<nb_edges, NT>>>(dst, deg);
    deg_rsqrt_kernel<<<nb_nodes, NT>>>(deg, dis);

    // pack inputs + weights
    pack_act_kernel<<<nb_pack, NT>>>(x, b1 /*unused*/, Ah, Al, 0);
    pack_w_kernel<<<nb_wpack, NT>>>(W1, B1h, B1l);
    pack_w_kernel<<<nb_wpack, NT>>>(W2, B2h, B2l);

    dim3 ggrid(4, MT);

    // Layer 1: hw -> bufA ; agg -> bufB ; pack h1 = relu(agg+b1)
    gemm_wmma_kernel<<<ggrid, 256>>>(Ah, Al, B1h, B1l, bufA);
    self_init_kernel<<<nb_elem4, NT>>>(bufA, dis, bufB);
    edge_agg_kernel<<<E_EDGES, 128>>>(bufA, src, dst, dis, bufB);
    pack_act_kernel<<<nb_pack, NT>>>(bufB, b1, Ah, Al, 1);

    // Layer 2: hw -> bufA ; agg -> bufB
    gemm_wmma_kernel<<<ggrid, 256>>>(Ah, Al, B2h, B2l, bufA);
    self_init_kernel<<<nb_elem4, NT>>>(bufA, dis, bufB);
    edge_agg_kernel<<<E_EDGES, 128>>>(bufA, src, dst, dis, bufB);

    // Heads (fused bias+relu)
    heads_kernel<<<(N_NODES + 7) / 8, 256>>>(bufB, b2, Wo, bo, Ww, bw, out);
}

// round 4
// speedup vs baseline: 2.4178x; 1.3293x over previous
#include <cuda_runtime.h>
#include <cuda_bf16.h>
#include <mma.h>
#include <cstdint>

using namespace nvcuda;

#define N_NODES 25000
#define E_EDGES 200000
#define HID 512
#define MT 196
#define MPAD (MT * 128)        // 25088

// ---------------------------------------------------------------------------
// Scratch (allocation-free: __device__ globals)
// ---------------------------------------------------------------------------
__device__ float g_bufA[MPAD * HID];            // hw (GEMM output)
__device__ float g_dis[N_NODES];
__device__ int   g_cnt[N_NODES];
__device__ int   g_off[N_NODES + 1];
__device__ int   g_cur[N_NODES];
__device__ int   g_csr_src[E_EDGES];
__device__ __nv_bfloat16 g_Ah[MPAD * HID];
__device__ __nv_bfloat16 g_Al[MPAD * HID];
__device__ __nv_bfloat16 g_B1h[HID * HID];
__device__ __nv_bfloat16 g_B1l[HID * HID];
__device__ __nv_bfloat16 g_B2h[HID * HID];
__device__ __nv_bfloat16 g_B2l[HID * HID];

// ---------------------------------------------------------------------------
// CSR build
// ---------------------------------------------------------------------------
__global__ void cnt_init_kernel(int* cnt) {
    int i = blockIdx.x * blockDim.x + threadIdx.x;
    if (i < N_NODES) cnt[i] = 0;
}
__global__ void cnt_count_kernel(const int* __restrict__ dst, int* cnt) {
    int e = blockIdx.x * blockDim.x + threadIdx.x;
    if (e < E_EDGES) atomicAdd(&cnt[dst[e]], 1);
}
__global__ void dis_kernel(const int* __restrict__ cnt, float* dis) {
    int i = blockIdx.x * blockDim.x + threadIdx.x;
    if (i < N_NODES) dis[i] = rsqrtf((float)cnt[i] + 1.0f);
}
// single-block exclusive scan -> off[0..N], off[N]=E
__global__ __launch_bounds__(1024)
void scan_kernel(const int* __restrict__ cnt, int* __restrict__ off) {
    __shared__ int part[1024];
    int t = threadIdx.x;
    const int CH = (N_NODES + 1023) / 1024;   // 25
    int base = t * CH;
    int s = 0;
    for (int i = 0; i < CH; i++) {
        int idx = base + i;
        if (idx < N_NODES) s += cnt[idx];
    }
    part[t] = s;
    __syncthreads();
    for (int d = 1; d < 1024; d <<= 1) {
        int v = (t >= d) ? part[t - d] : 0;
        __syncthreads();
        part[t] += v;
        __syncthreads();
    }
    int run = part[t] - s;    // exclusive prefix
    for (int i = 0; i < CH; i++) {
        int idx = base + i;
        if (idx < N_NODES) {
            off[idx] = run;
            run += cnt[idx];
        }
    }
    if (t == 1023) off[N_NODES] = run;
}
__global__ void cur_init_kernel(const int* __restrict__ off, int* cur) {
    int i = blockIdx.x * blockDim.x + threadIdx.x;
    if (i < N_NODES) cur[i] = off[i];
}
__global__ void scatter_kernel(const int* __restrict__ src, const int* __restrict__ dst,
                               int* cur, int* __restrict__ csr_src) {
    int e = blockIdx.x * blockDim.x + threadIdx.x;
    if (e >= E_EDGES) return;
    int pos = atomicAdd(&cur[dst[e]], 1);
    csr_src[pos] = src[e];
}

// ---------------------------------------------------------------------------
// Pack x [MPAD][512] fp32 -> bf16 hi/lo (row-major), zero-pads rows >= N_NODES
// ---------------------------------------------------------------------------
__global__ __launch_bounds__(256)
void pack_x_kernel(const float* __restrict__ src,
                   __nv_bfloat16* __restrict__ outH, __nv_bfloat16* __restrict__ outL) {
    int idx = blockIdx.x * blockDim.x + threadIdx.x;
    if (idx >= MPAD * 256) return;
    int m = idx >> 8;
    int k = (idx & 255) * 2;

    float v0 = 0.f, v1 = 0.f;
    if (m < N_NODES) {
        float2 v = *(const float2*)(src + (size_t)m * HID + k);
        v0 = v.x; v1 = v.y;
    }
    __nv_bfloat16 h0 = __float2bfloat16_rn(v0);
    __nv_bfloat16 h1 = __float2bfloat16_rn(v1);
    __nv_bfloat16 l0 = __float2bfloat16_rn(v0 - __bfloat162float(h0));
    __nv_bfloat16 l1 = __float2bfloat16_rn(v1 - __bfloat162float(h1));

    size_t off = (size_t)m * HID + k;
    *(__nv_bfloat162*)(outH + off) = __nv_bfloat162(h0, h1);
    *(__nv_bfloat162*)(outL + off) = __nv_bfloat162(l0, l1);
}

__global__ __launch_bounds__(256)
void pack_w_kernel(const float* __restrict__ W,
                   __nv_bfloat16* __restrict__ outH, __nv_bfloat16* __restrict__ outL) {
    int idx = blockIdx.x * blockDim.x + threadIdx.x;
    if (idx >= 512 * 256) return;
    int k = idx >> 8;
    int n = (idx & 255) * 2;

    float2 v = *(const float2*)(W + (size_t)k * HID + n);
    __nv_bfloat16 h0 = __float2bfloat16_rn(v.x);
    __nv_bfloat16 h1 = __float2bfloat16_rn(v.y);
    __nv_bfloat16 l0 = __float2bfloat16_rn(v.x - __bfloat162float(h0));
    __nv_bfloat16 l1 = __float2bfloat16_rn(v.y - __bfloat162float(h1));

    size_t off = (size_t)k * HID + n;
    *(__nv_bfloat162*)(outH + off) = __nv_bfloat162(h0, h1);
    *(__nv_bfloat162*)(outL + off) = __nv_bfloat162(l0, l1);
}

// ---------------------------------------------------------------------------
// WMMA bf16-split GEMM (unchanged from R3): C = A @ B, fp32 out
// ---------------------------------------------------------------------------
__global__ __launch_bounds__(256)
void gemm_wmma_kernel(const __nv_bfloat16* __restrict__ Ah, const __nv_bfloat16* __restrict__ Al,
                      const __nv_bfloat16* __restrict__ Bh, const __nv_bfloat16* __restrict__ Bl,
                      float* __restrict__ C) {
    __shared__ __nv_bfloat16 Ash[128][40];
    __shared__ __nv_bfloat16 Asl[128][40];
    __shared__ __nv_bfloat16 Bsh[32][136];
    __shared__ __nv_bfloat16 Bsl[32][136];

    int tid = threadIdx.x;
    int bm = blockIdx.y * 128;
    int bn = blockIdx.x * 128;
    int wid = tid >> 5;
    int wm = (wid & 3) * 32;
    int wn = (wid >> 2) * 64;

    wmma::fragment<wmma::accumulator, 16, 16, 16, float> acc[2][4];
    #pragma unroll
    for (int i = 0; i < 2; i++)
        #pragma unroll
        for (int j = 0; j < 4; j++)
            wmma::fill_fragment(acc[i][j], 0.0f);

    int arow = tid >> 2;
    int acol = (tid & 3) * 8;
    int brow = tid >> 4;
    int bcol = (tid & 15) * 8;

    for (int k0 = 0; k0 < 512; k0 += 32) {
        #pragma unroll
        for (int r = 0; r < 2; r++) {
            int row = arow + r * 64;
            size_t g = (size_t)(bm + row) * HID + k0 + acol;
            *(uint4*)&Ash[row][acol] = *(const uint4*)(Ah + g);
            *(uint4*)&Asl[row][acol] = *(const uint4*)(Al + g);
        }
        #pragma unroll
        for (int r = 0; r < 2; r++) {
            int row = brow + r * 16;
            size_t g = (size_t)(k0 + row) * HID + bn + bcol;
            *(uint4*)&Bsh[row][bcol] = *(const uint4*)(Bh + g);
            *(uint4*)&Bsl[row][bcol] = *(const uint4*)(Bl + g);
        }
        __syncthreads();

        #pragma unroll
        for (int kk = 0; kk < 32; kk += 16) {
            wmma::fragment<wmma::matrix_a, 16, 16, 16, __nv_bfloat16, wmma::row_major> fa_h[2], fa_l[2];
            wmma::fragment<wmma::matrix_b, 16, 16, 16, __nv_bfloat16, wmma::row_major> fb_h[4], fb_l[4];
            #pragma unroll
            for (int i = 0; i < 2; i++) {
                wmma::load_matrix_sync(fa_h[i], &Ash[wm + i * 16][kk], 40);
                wmma::load_matrix_sync(fa_l[i], &Asl[wm + i * 16][kk], 40);
            }
            #pragma unroll
            for (int j = 0; j < 4; j++) {
                wmma::load_matrix_sync(fb_h[j], &Bsh[kk][wn + j * 16], 136);
                wmma::load_matrix_sync(fb_l[j], &Bsl[kk][wn + j * 16], 136);
            }
            #pragma unroll
            for (int i = 0; i < 2; i++)
                #pragma unroll
                for (int j = 0; j < 4; j++) {
                    wmma::mma_sync(acc[i][j], fa_h[i], fb_h[j], acc[i][j]);
                    wmma::mma_sync(acc[i][j], fa_l[i], fb_h[j], acc[i][j]);
                    wmma::mma_sync(acc[i][j], fa_h[i], fb_l[j], acc[i][j]);
                }
        }
        __syncthreads();
    }

    #pragma unroll
    for (int i = 0; i < 2; i++)
        #pragma unroll
        for (int j = 0; j < 4; j++)
            wmma::store_matrix_sync(C + (size_t)(bm + wm + i * 16) * HID + bn + wn + j * 16,
                                    acc[i][j], HID, wmma::mem_row_major);
}

// ---------------------------------------------------------------------------
// Layer-1 gather: one block per node.
// agg = sum_{e:dst=n} hw[src]*dis[src]*dis[n] + hw[n]*dis[n]^2
// h1 = relu(agg + b1)  ->  packed bf16 hi/lo into Ah/Al
// ---------------------------------------------------------------------------
__global__ __launch_bounds__(128)
void gather_pack_kernel(const float* __restrict__ hw,
                        const int* __restrict__ off, const int* __restrict__ csr_src,
                        const float* __restrict__ dis, const float* __restrict__ bias,
                        __nv_bfloat16* __restrict__ outH, __nv_bfloat16* __restrict__ outL) {
    int n = blockIdx.x;
    int t = threadIdx.x;
    float dn = __ldg(&dis[n]);

    const float4* hn = (const float4*)(hw + (size_t)n * HID);
    float4 v = hn[t];
    float dd = dn * dn;
    float4 acc = make_float4(v.x * dd, v.y * dd, v.z * dd, v.w * dd);

    int beg = __ldg(&off[n]), end = __ldg(&off[n + 1]);
    for (int j = beg; j < end; j++) {
        int s = __ldg(&csr_src[j]);
        float nrm = __ldg(&dis[s]) * dn;
        float4 h = ((const float4*)(hw + (size_t)s * HID))[t];
        acc.x = fmaf(h.x, nrm, acc.x);
        acc.y = fmaf(h.y, nrm, acc.y);
        acc.z = fmaf(h.z, nrm, acc.z);
        acc.w = fmaf(h.w, nrm, acc.w);
    }

    int c = t * 4;
    float4 b = *(const float4*)(bias + c);
    float r0 = fmaxf(acc.x + b.x, 0.f);
    float r1 = fmaxf(acc.y + b.y, 0.f);
    float r2 = fmaxf(acc.z + b.z, 0.f);
    float r3 = fmaxf(acc.w + b.w, 0.f);

    __nv_bfloat16 h0 = __float2bfloat16_rn(r0), h1 = __float2bfloat16_rn(r1);
    __nv_bfloat16 h2 = __float2bfloat16_rn(r2), h3 = __float2bfloat16_rn(r3);
    __nv_bfloat16 l0 = __float2bfloat16_rn(r0 - __bfloat162float(h0));
    __nv_bfloat16 l1 = __float2bfloat16_rn(r1 - __bfloat162float(h1));
    __nv_bfloat16 l2 = __float2bfloat16_rn(r2 - __bfloat162float(h2));
    __nv_bfloat16 l3 = __float2bfloat16_rn(r3 - __bfloat162float(h3));

    size_t o = (size_t)n * HID + c;
    __nv_bfloat162 ph0(h0, h1), ph1(h2, h3), pl0(l0, l1), pl1(l2, l3);
    uint2 uh = make_uint2(*(uint32_t*)&ph0, *(uint32_t*)&ph1);
    uint2 ul = make_uint2(*(uint32_t*)&pl0, *(uint32_t*)&pl1);
    *(uint2*)(outH + o) = uh;
    *(uint2*)(outL + o) = ul;
}

// ---------------------------------------------------------------------------
// Layer-2 gather + heads: one block per node.
// h2 = relu(agg + b2) ; out[n] = h2·Wo + bo ; out[N+n] = h2·Ww + bw
// ---------------------------------------------------------------------------
__global__ __launch_bounds__(128)
void gather_heads_kernel(const float* __restrict__ hw,
                         const int* __restrict__ off, const int* __restrict__ csr_src,
                         const float* __restrict__ dis, const float* __restrict__ bias,
                         const float* __restrict__ Wo, const float* __restrict__ bo,
                         const float* __restrict__ Ww, const float* __restrict__ bw,
                         float* __restrict__ out) {
    __shared__ float red[8];
    int n = blockIdx.x;
    int t = threadIdx.x;
    float dn = __ldg(&dis[n]);

    const float4* hn = (const float4*)(hw + (size_t)n * HID);
    float4 v = hn[t];
    float dd = dn * dn;
    float4 acc = make_float4(v.x * dd, v.y * dd, v.z * dd, v.w * dd);

    int beg = __ldg(&off[n]), end = __ldg(&off[n + 1]);
    for (int j = beg; j < end; j++) {
        int s = __ldg(&csr_src[j]);
        float nrm = __ldg(&dis[s]) * dn;
        float4 h = ((const float4*)(hw + (size_t)s * HID))[t];
        acc.x = fmaf(h.x, nrm, acc.x);
        acc.y = fmaf(h.y, nrm, acc.y);
        acc.z = fmaf(h.z, nrm, acc.z);
        acc.w = fmaf(h.w, nrm, acc.w);
    }

    int c = t * 4;
    float4 b  = *(const float4*)(bias + c);
    float4 wo = *(const float4*)(Wo + c);
    float4 ww = *(const float4*)(Ww + c);
    float r0 = fmaxf(acc.x + b.x, 0.f);
    float r1 = fmaxf(acc.y + b.y, 0.f);
    float r2 = fmaxf(acc.z + b.z, 0.f);
    float r3 = fmaxf(acc.w + b.w, 0.f);

    float so = r0 * wo.x + r1 * wo.y + r2 * wo.z + r3 * wo.w;
    float sw = r0 * ww.x + r1 * ww.y + r2 * ww.z + r3 * ww.w;

    #pragma unroll
    for (int o2 = 16; o2; o2 >>= 1) {
        so += __shfl_down_sync(0xffffffff, so, o2);
        sw += __shfl_down_sync(0xffffffff, sw, o2);
    }
    int warp = t >> 5, lane = t & 31;
    if (lane == 0) { red[warp] = so; red[4 + warp] = sw; }
    __syncthreads();
    if (t == 0) {
        float fo = red[0] + red[1] + red[2] + red[3];
        float fw = red[4] + red[5] + red[6] + red[7];
        out[n]           = fo + bo[0];
        out[N_NODES + n] = fw + bw[0];
    }
}

// ---------------------------------------------------------------------------
// Launch
// ---------------------------------------------------------------------------
extern "C" void kernel_launch(void* const* d_in, const int* in_sizes, int n_in,
                              void* d_out, int out_size) {
    const float* x  = (const float*)d_in[0];
    const int*   ei = (const int*)d_in[1];
    const float* W1 = (const float*)d_in[2];
    const float* b1 = (const float*)d_in[3];
    const float* W2 = (const float*)d_in[4];
    const float* b2 = (const float*)d_in[5];
    const float* Wo = (const float*)d_in[6];
    const float* bo = (const float*)d_in[7];
    const float* Ww = (const float*)d_in[8];
    const float* bw = (const float*)d_in[9];

    const int* src = ei;
    const int* dst = ei + E_EDGES;
    float* out = (float*)d_out;

    float *bufA, *dis;
    int *cnt, *off, *cur, *csr_src;
    __nv_bfloat16 *Ah, *Al, *B1h, *B1l, *B2h, *B2l;
    cudaGetSymbolAddress((void**)&bufA, g_bufA);
    cudaGetSymbolAddress((void**)&dis,  g_dis);
    cudaGetSymbolAddress((void**)&cnt,  g_cnt);
    cudaGetSymbolAddress((void**)&off,  g_off);
    cudaGetSymbolAddress((void**)&cur,  g_cur);
    cudaGetSymbolAddress((void**)&csr_src, g_csr_src);
    cudaGetSymbolAddress((void**)&Ah,   g_Ah);
    cudaGetSymbolAddress((void**)&Al,   g_Al);
    cudaGetSymbolAddress((void**)&B1h,  g_B1h);
    cudaGetSymbolAddress((void**)&B1l,  g_B1l);
    cudaGetSymbolAddress((void**)&B2h,  g_B2h);
    cudaGetSymbolAddress((void**)&B2l,  g_B2l);

    const int NT = 256;
    int nb_nodes = (N_NODES + NT - 1) / NT;
    int nb_edges = (E_EDGES + NT - 1) / NT;
    int nb_pack  = (MPAD * 256 + NT - 1) / NT;
    int nb_wpack = (512 * 256 + NT - 1) / NT;

    // CSR + norms
    cnt_init_kernel<<<nb_nodes, NT>>>(cnt);
    cnt_count_kernel<<<nb_edges, NT>>>(dst, cnt);
    dis_kernel<<<nb_nodes, NT>>>(cnt, dis);
    scan_kernel<<<1, 1024>>>(cnt, off);
    cur_init_kernel<<<nb_nodes, NT>>>(off, cur);
    scatter_kernel<<<nb_edges, NT>>>(src, dst, cur, csr_src);

    // pack inputs + weights
    pack_x_kernel<<<nb_pack, NT>>>(x, Ah, Al);
    pack_w_kernel<<<nb_wpack, NT>>>(W1, B1h, B1l);
    pack_w_kernel<<<nb_wpack, NT>>>(W2, B2h, B2l);

    dim3 ggrid(4, MT);

    // Layer 1: hw1 -> bufA ; gather+bias+relu+pack -> Ah/Al
    gemm_wmma_kernel<<<ggrid, 256>>>(Ah, Al, B1h, B1l, bufA);
    gather_pack_kernel<<<N_NODES, 128>>>(bufA, off, csr_src, dis, b1, Ah, Al);

    // Layer 2: hw2 -> bufA ; gather+bias+relu+heads -> out
    gemm_wmma_kernel<<<ggrid, 256>>>(Ah, Al, B2h, B2l, bufA);
    gather_heads_kernel<<<N_NODES, 128>>>(bufA, off, csr_src, dis, b2,
                                          Wo, bo, Ww, bw, out);
}

// round 5
// speedup vs baseline: 2.5817x; 1.0678x over previous
#include <cuda_runtime.h>
#include <cuda_bf16.h>
#include <mma.h>
#include <cstdint>

using namespace nvcuda;

#define N_NODES 25000
#define E_EDGES 200000
#define HID 512
#define MT 196
#define MPAD (MT * 128)        // 25088

// ---------------------------------------------------------------------------
// Scratch (allocation-free: __device__ globals)
// ---------------------------------------------------------------------------
__device__ float g_bufA[MPAD * HID];            // hw (GEMM output)
__device__ float g_dis[N_NODES];
__device__ int   g_cnt[N_NODES];
__device__ int   g_off[N_NODES + 1];
__device__ int   g_cur[N_NODES];
__device__ int   g_csr_src[E_EDGES];
__device__ __nv_bfloat16 g_Ah[MPAD * HID];
__device__ __nv_bfloat16 g_Al[MPAD * HID];
__device__ __nv_bfloat16 g_B1h[HID * HID];
__device__ __nv_bfloat16 g_B1l[HID * HID];
__device__ __nv_bfloat16 g_B2h[HID * HID];
__device__ __nv_bfloat16 g_B2l[HID * HID];

// ---------------------------------------------------------------------------
// CSR build
// ---------------------------------------------------------------------------
__global__ void cnt_init_kernel(int* cnt) {
    int i = blockIdx.x * blockDim.x + threadIdx.x;
    if (i < N_NODES) cnt[i] = 0;
}
__global__ void cnt_count_kernel(const int* __restrict__ dst, int* cnt) {
    int e = blockIdx.x * blockDim.x + threadIdx.x;
    if (e < E_EDGES) atomicAdd(&cnt[dst[e]], 1);
}
__global__ void dis_kernel(const int* __restrict__ cnt, float* dis) {
    int i = blockIdx.x * blockDim.x + threadIdx.x;
    if (i < N_NODES) dis[i] = rsqrtf((float)cnt[i] + 1.0f);
}
// single-block exclusive scan, warp-shuffle based
__global__ __launch_bounds__(1024)
void scan_kernel(const int* __restrict__ cnt, int* __restrict__ off) {
    __shared__ int wsum[32];
    int t = threadIdx.x, lane = t & 31, warp = t >> 5;
    const int CH = (N_NODES + 1023) / 1024;   // 25
    int base = t * CH;

    int s = 0;
    #pragma unroll
    for (int i = 0; i < CH; i++) {
        int idx = base + i;
        if (idx < N_NODES) s += cnt[idx];
    }
    // inclusive warp scan
    int incl = s;
    #pragma unroll
    for (int d = 1; d < 32; d <<= 1) {
        int v = __shfl_up_sync(0xffffffff, incl, d);
        if (lane >= d) incl += v;
    }
    if (lane == 31) wsum[warp] = incl;
    __syncthreads();
    if (warp == 0) {
        int w = wsum[lane];
        #pragma unroll
        for (int d = 1; d < 32; d <<= 1) {
            int v = __shfl_up_sync(0xffffffff, w, d);
            if (lane >= d) w += v;
        }
        wsum[lane] = w;
    }
    __syncthreads();

    int run = incl - s + (warp ? wsum[warp - 1] : 0);   // exclusive prefix
    #pragma unroll
    for (int i = 0; i < CH; i++) {
        int idx = base + i;
        if (idx < N_NODES) {
            off[idx] = run;
            run += cnt[idx];
        }
    }
    if (t == 1023) off[N_NODES] = wsum[31];
}
__global__ void cur_init_kernel(const int* __restrict__ off, int* cur) {
    int i = blockIdx.x * blockDim.x + threadIdx.x;
    if (i < N_NODES) cur[i] = off[i];
}
__global__ void scatter_kernel(const int* __restrict__ src, const int* __restrict__ dst,
                               int* cur, int* __restrict__ csr_src) {
    int e = blockIdx.x * blockDim.x + threadIdx.x;
    if (e >= E_EDGES) return;
    int pos = atomicAdd(&cur[dst[e]], 1);
    csr_src[pos] = src[e];
}

// ---------------------------------------------------------------------------
// Pack x -> bf16 hi/lo, zero-pads rows >= N_NODES
// ---------------------------------------------------------------------------
__global__ __launch_bounds__(256)
void pack_x_kernel(const float* __restrict__ src,
                   __nv_bfloat16* __restrict__ outH, __nv_bfloat16* __restrict__ outL) {
    int idx = blockIdx.x * blockDim.x + threadIdx.x;
    if (idx >= MPAD * 256) return;
    int m = idx >> 8;
    int k = (idx & 255) * 2;

    float v0 = 0.f, v1 = 0.f;
    if (m < N_NODES) {
        float2 v = *(const float2*)(src + (size_t)m * HID + k);
        v0 = v.x; v1 = v.y;
    }
    __nv_bfloat16 h0 = __float2bfloat16_rn(v0);
    __nv_bfloat16 h1 = __float2bfloat16_rn(v1);
    __nv_bfloat16 l0 = __float2bfloat16_rn(v0 - __bfloat162float(h0));
    __nv_bfloat16 l1 = __float2bfloat16_rn(v1 - __bfloat162float(h1));

    size_t off = (size_t)m * HID + k;
    *(__nv_bfloat162*)(outH + off) = __nv_bfloat162(h0, h1);
    *(__nv_bfloat162*)(outL + off) = __nv_bfloat162(l0, l1);
}

__global__ __launch_bounds__(256)
void pack_w_kernel(const float* __restrict__ W,
                   __nv_bfloat16* __restrict__ outH, __nv_bfloat16* __restrict__ outL) {
    int idx = blockIdx.x * blockDim.x + threadIdx.x;
    if (idx >= 512 * 256) return;
    int k = idx >> 8;
    int n = (idx & 255) * 2;

    float2 v = *(const float2*)(W + (size_t)k * HID + n);
    __nv_bfloat16 h0 = __float2bfloat16_rn(v.x);
    __nv_bfloat16 h1 = __float2bfloat16_rn(v.y);
    __nv_bfloat16 l0 = __float2bfloat16_rn(v.x - __bfloat162float(h0));
    __nv_bfloat16 l1 = __float2bfloat16_rn(v.y - __bfloat162float(h1));

    size_t off = (size_t)k * HID + n;
    *(__nv_bfloat162*)(outH + off) = __nv_bfloat162(h0, h1);
    *(__nv_bfloat162*)(outL + off) = __nv_bfloat162(l0, l1);
}

// ---------------------------------------------------------------------------
// cp.async helpers
// ---------------------------------------------------------------------------
__device__ __forceinline__ void cpa16(uint32_t dst, const void* src) {
    asm volatile("cp.async.cg.shared.global [%0], [%1], 16;" :: "r"(dst), "l"(src));
}
__device__ __forceinline__ void cpa_commit() {
    asm volatile("cp.async.commit_group;" ::: "memory");
}
__device__ __forceinline__ void cpa_wait0() {
    asm volatile("cp.async.wait_group 0;" ::: "memory");
}

// ---------------------------------------------------------------------------
// WMMA bf16-split GEMM, 2-stage cp.async pipeline.
// Block 128x128, BK=32, 8 warps (4m x 2n), warp tile 32x64.
// Dynamic smem: per stage  Ah[128][40] Al[128][40] Bh[32][136] Bl[32][136]
// ---------------------------------------------------------------------------
#define AS_STRIDE 40
#define BS_STRIDE 136
#define A_TILE_ELE (128 * AS_STRIDE)          // 5120
#define B_TILE_ELE (32 * BS_STRIDE)           // 4352
#define STAGE_ELE  (2 * A_TILE_ELE + 2 * B_TILE_ELE)   // 18944 bf16
#define GEMM_SMEM_BYTES (2 * STAGE_ELE * 2)            // 75776 B

__global__ __launch_bounds__(256)
void gemm_wmma_kernel(const __nv_bfloat16* __restrict__ Ah, const __nv_bfloat16* __restrict__ Al,
                      const __nv_bfloat16* __restrict__ Bh, const __nv_bfloat16* __restrict__ Bl,
                      float* __restrict__ C) {
    extern __shared__ __nv_bfloat16 smem[];

    int tid = threadIdx.x;
    int bm = blockIdx.y * 128;
    int bn = blockIdx.x * 128;
    int wid = tid >> 5;
    int wm = (wid & 3) * 32;
    int wn = (wid >> 2) * 64;

    wmma::fragment<wmma::accumulator, 16, 16, 16, float> acc[2][4];
    #pragma unroll
    for (int i = 0; i < 2; i++)
        #pragma unroll
        for (int j = 0; j < 4; j++)
            wmma::fill_fragment(acc[i][j], 0.0f);

    // load assignment
    // A: 512 16B-chunks per array: chunk c -> row=c>>2, col8=(c&3)*8 ; thread does c=tid, tid+256
    // B: 512 16B-chunks per array: chunk c -> row=c>>4, col8=(c&15)*8
    int a_r0 = tid >> 2,  a_c0 = (tid & 3) * 8;
    int a_r1 = (tid + 256) >> 2, a_c1 = ((tid + 256) & 3) * 8;
    int b_r0 = tid >> 4,  b_c0 = (tid & 15) * 8;
    int b_r1 = (tid + 256) >> 4, b_c1 = ((tid + 256) & 15) * 8;

    uint32_t sbase = (uint32_t)__cvta_generic_to_shared(smem);

    auto load_stage = [&](int stage, int k0) {
        uint32_t st = sbase + (uint32_t)(stage * STAGE_ELE) * 2;
        uint32_t sAh = st;
        uint32_t sAl = st + A_TILE_ELE * 2;
        uint32_t sBh = st + 2 * A_TILE_ELE * 2;
        uint32_t sBl = st + (2 * A_TILE_ELE + B_TILE_ELE) * 2;

        const __nv_bfloat16* gA = Ah + (size_t)bm * HID + k0;
        const __nv_bfloat16* gAl2 = Al + (size_t)bm * HID + k0;
        const __nv_bfloat16* gB = Bh + (size_t)k0 * HID + bn;
        const __nv_bfloat16* gBl2 = Bl + (size_t)k0 * HID + bn;

        cpa16(sAh + (uint32_t)(a_r0 * AS_STRIDE + a_c0) * 2, gA  + (size_t)a_r0 * HID + a_c0);
        cpa16(sAh + (uint32_t)(a_r1 * AS_STRIDE + a_c1) * 2, gA  + (size_t)a_r1 * HID + a_c1);
        cpa16(sAl + (uint32_t)(a_r0 * AS_STRIDE + a_c0) * 2, gAl2 + (size_t)a_r0 * HID + a_c0);
        cpa16(sAl + (uint32_t)(a_r1 * AS_STRIDE + a_c1) * 2, gAl2 + (size_t)a_r1 * HID + a_c1);
        cpa16(sBh + (uint32_t)(b_r0 * BS_STRIDE + b_c0) * 2, gB  + (size_t)b_r0 * HID + b_c0);
        cpa16(sBh + (uint32_t)(b_r1 * BS_STRIDE + b_c1) * 2, gB  + (size_t)b_r1 * HID + b_c1);
        cpa16(sBl + (uint32_t)(b_r0 * BS_STRIDE + b_c0) * 2, gBl2 + (size_t)b_r0 * HID + b_c0);
        cpa16(sBl + (uint32_t)(b_r1 * BS_STRIDE + b_c1) * 2, gBl2 + (size_t)b_r1 * HID + b_c1);
        cpa_commit();
    };

    load_stage(0, 0);
    int buf = 0;

    for (int it = 0; it < 16; it++) {
        cpa_wait0();
        __syncthreads();
        if (it + 1 < 16) load_stage(buf ^ 1, (it + 1) * 32);

        __nv_bfloat16* st = smem + buf * STAGE_ELE;
        __nv_bfloat16* Ash = st;
        __nv_bfloat16* Asl = st + A_TILE_ELE;
        __nv_bfloat16* Bsh = st + 2 * A_TILE_ELE;
        __nv_bfloat16* Bsl = st + 2 * A_TILE_ELE + B_TILE_ELE;

        #pragma unroll
        for (int kk = 0; kk < 32; kk += 16) {
            wmma::fragment<wmma::matrix_a, 16, 16, 16, __nv_bfloat16, wmma::row_major> fa_h[2], fa_l[2];
            wmma::fragment<wmma::matrix_b, 16, 16, 16, __nv_bfloat16, wmma::row_major> fb_h[4], fb_l[4];
            #pragma unroll
            for (int i = 0; i < 2; i++) {
                wmma::load_matrix_sync(fa_h[i], Ash + (wm + i * 16) * AS_STRIDE + kk, AS_STRIDE);
                wmma::load_matrix_sync(fa_l[i], Asl + (wm + i * 16) * AS_STRIDE + kk, AS_STRIDE);
            }
            #pragma unroll
            for (int j = 0; j < 4; j++) {
                wmma::load_matrix_sync(fb_h[j], Bsh + kk * BS_STRIDE + wn + j * 16, BS_STRIDE);
                wmma::load_matrix_sync(fb_l[j], Bsl + kk * BS_STRIDE + wn + j * 16, BS_STRIDE);
            }
            #pragma unroll
            for (int i = 0; i < 2; i++)
                #pragma unroll
                for (int j = 0; j < 4; j++) {
                    wmma::mma_sync(acc[i][j], fa_h[i], fb_h[j], acc[i][j]);
                    wmma::mma_sync(acc[i][j], fa_l[i], fb_h[j], acc[i][j]);
                    wmma::mma_sync(acc[i][j], fa_h[i], fb_l[j], acc[i][j]);
                }
        }
        __syncthreads();
        buf ^= 1;
    }

    #pragma unroll
    for (int i = 0; i < 2; i++)
        #pragma unroll
        for (int j = 0; j < 4; j++)
            wmma::store_matrix_sync(C + (size_t)(bm + wm + i * 16) * HID + bn + wn + j * 16,
                                    acc[i][j], HID, wmma::mem_row_major);
}

// ---------------------------------------------------------------------------
// Gather with smem-staged indices + unrolled MLP accumulate
// ---------------------------------------------------------------------------
#define GCH 32

__device__ __forceinline__ float4 gather_node(const float* __restrict__ hw,
                                              const int* __restrict__ off,
                                              const int* __restrict__ csr_src,
                                              const float* __restrict__ dis,
                                              int n, int t, float dn,
                                              int* s_idx, float* s_nrm) {
    const float4* hn = (const float4*)(hw + (size_t)n * HID);
    float4 v = hn[t];
    float dd = dn * dn;
    float4 acc = make_float4(v.x * dd, v.y * dd, v.z * dd, v.w * dd);

    int beg = __ldg(&off[n]), end = __ldg(&off[n + 1]);
    for (int base = beg; base < end; base += GCH) {
        int m = min(GCH, end - base);
        __syncthreads();
        if (t < m) {
            int s = __ldg(&csr_src[base + t]);
            s_idx[t] = s;
            s_nrm[t] = __ldg(&dis[s]) * dn;
        }
        __syncthreads();
        #pragma unroll 4
        for (int j = 0; j < m; j++) {
            int s = s_idx[j];
            float nrm = s_nrm[j];
            float4 h = ((const float4*)(hw + (size_t)s * HID))[t];
            acc.x = fmaf(h.x, nrm, acc.x);
            acc.y = fmaf(h.y, nrm, acc.y);
            acc.z = fmaf(h.z, nrm, acc.z);
            acc.w = fmaf(h.w, nrm, acc.w);
        }
    }
    return acc;
}

__global__ __launch_bounds__(128)
void gather_pack_kernel(const float* __restrict__ hw,
                        const int* __restrict__ off, const int* __restrict__ csr_src,
                        const float* __restrict__ dis, const float* __restrict__ bias,
                        __nv_bfloat16* __restrict__ outH, __nv_bfloat16* __restrict__ outL) {
    __shared__ int s_idx[GCH];
    __shared__ float s_nrm[GCH];
    int n = blockIdx.x;
    int t = threadIdx.x;
    float dn = __ldg(&dis[n]);

    float4 acc = gather_node(hw, off, csr_src, dis, n, t, dn, s_idx, s_nrm);

    int c = t * 4;
    float4 b = *(const float4*)(bias + c);
    float r0 = fmaxf(acc.x + b.x, 0.f);
    float r1 = fmaxf(acc.y + b.y, 0.f);
    float r2 = fmaxf(acc.z + b.z, 0.f);
    float r3 = fmaxf(acc.w + b.w, 0.f);

    __nv_bfloat16 h0 = __float2bfloat16_rn(r0), h1 = __float2bfloat16_rn(r1);
    __nv_bfloat16 h2 = __float2bfloat16_rn(r2), h3 = __float2bfloat16_rn(r3);
    __nv_bfloat16 l0 = __float2bfloat16_rn(r0 - __bfloat162float(h0));
    __nv_bfloat16 l1 = __float2bfloat16_rn(r1 - __bfloat162float(h1));
    __nv_bfloat16 l2 = __float2bfloat16_rn(r2 - __bfloat162float(h2));
    __nv_bfloat16 l3 = __float2bfloat16_rn(r3 - __bfloat162float(h3));

    size_t o = (size_t)n * HID + c;
    __nv_bfloat162 ph0(h0, h1), ph1(h2, h3), pl0(l0, l1), pl1(l2, l3);
    uint2 uh = make_uint2(*(uint32_t*)&ph0, *(uint32_t*)&ph1);
    uint2 ul = make_uint2(*(uint32_t*)&pl0, *(uint32_t*)&pl1);
    *(uint2*)(outH + o) = uh;
    *(uint2*)(outL + o) = ul;
}

__global__ __launch_bounds__(128)
void gather_heads_kernel(const float* __restrict__ hw,
                         const int* __restrict__ off, const int* __restrict__ csr_src,
                         const float* __restrict__ dis, const float* __restrict__ bias,
                         const float* __restrict__ Wo, const float* __restrict__ bo,
                         const float* __restrict__ Ww, const float* __restrict__ bw,
                         float* __restrict__ out) {
    __shared__ int s_idx[GCH];
    __shared__ float s_nrm[GCH];
    __shared__ float red[8];
    int n = blockIdx.x;
    int t = threadIdx.x;
    float dn = __ldg(&dis[n]);

    float4 acc = gather_node(hw, off, csr_src, dis, n, t, dn, s_idx, s_nrm);

    int c = t * 4;
    float4 b  = *(const float4*)(bias + c);
    float4 wo = *(const float4*)(Wo + c);
    float4 ww = *(const float4*)(Ww + c);
    float r0 = fmaxf(acc.x + b.x, 0.f);
    float r1 = fmaxf(acc.y + b.y, 0.f);
    float r2 = fmaxf(acc.z + b.z, 0.f);
    float r3 = fmaxf(acc.w + b.w, 0.f);

    float so = r0 * wo.x + r1 * wo.y + r2 * wo.z + r3 * wo.w;
    float sw = r0 * ww.x + r1 * ww.y + r2 * ww.z + r3 * ww.w;

    #pragma unroll
    for (int o2 = 16; o2; o2 >>= 1) {
        so += __shfl_down_sync(0xffffffff, so, o2);
        sw += __shfl_down_sync(0xffffffff, sw, o2);
    }
    int warp = t >> 5, lane = t & 31;
    if (lane == 0) { red[warp] = so; red[4 + warp] = sw; }
    __syncthreads();
    if (t == 0) {
        float fo = red[0] + red[1] + red[2] + red[3];
        float fw = red[4] + red[5] + red[6] + red[7];
        out[n]           = fo + bo[0];
        out[N_NODES + n] = fw + bw[0];
    }
}

// ---------------------------------------------------------------------------
// Launch
// ---------------------------------------------------------------------------
extern "C" void kernel_launch(void* const* d_in, const int* in_sizes, int n_in,
                              void* d_out, int out_size) {
    const float* x  = (const float*)d_in[0];
    const int*   ei = (const int*)d_in[1];
    const float* W1 = (const float*)d_in[2];
    const float* b1 = (const float*)d_in[3];
    const float* W2 = (const float*)d_in[4];
    const float* b2 = (const float*)d_in[5];
    const float* Wo = (const float*)d_in[6];
    const float* bo = (const float*)d_in[7];
    const float* Ww = (const float*)d_in[8];
    const float* bw = (const float*)d_in[9];

    const int* src = ei;
    const int* dst = ei + E_EDGES;
    float* out = (float*)d_out;

    float *bufA, *dis;
    int *cnt, *off, *cur, *csr_src;
    __nv_bfloat16 *Ah, *Al, *B1h, *B1l, *B2h, *B2l;
    cudaGetSymbolAddress((void**)&bufA, g_bufA);
    cudaGetSymbolAddress((void**)&dis,  g_dis);
    cudaGetSymbolAddress((void**)&cnt,  g_cnt);
    cudaGetSymbolAddress((void**)&off,  g_off);
    cudaGetSymbolAddress((void**)&cur,  g_cur);
    cudaGetSymbolAddress((void**)&csr_src, g_csr_src);
    cudaGetSymbolAddress((void**)&Ah,   g_Ah);
    cudaGetSymbolAddress((void**)&Al,   g_Al);
    cudaGetSymbolAddress((void**)&B1h,  g_B1h);
    cudaGetSymbolAddress((void**)&B1l,  g_B1l);
    cudaGetSymbolAddress((void**)&B2h,  g_B2h);
    cudaGetSymbolAddress((void**)&B2l,  g_B2l);

    cudaFuncSetAttribute(gemm_wmma_kernel, cudaFuncAttributeMaxDynamicSharedMemorySize,
                         GEMM_SMEM_BYTES);

    const int NT = 256;
    int nb_nodes = (N_NODES + NT - 1) / NT;
    int nb_edges = (E_EDGES + NT - 1) / NT;
    int nb_pack  = (MPAD * 256 + NT - 1) / NT;
    int nb_wpack = (512 * 256 + NT - 1) / NT;

    // CSR + norms
    cnt_init_kernel<<<nb_nodes, NT>>>(cnt);
    cnt_count_kernel<<<nb_edges, NT>>>(dst, cnt);
    dis_kernel<<<nb_nodes, NT>>>(cnt, dis);
    scan_kernel<<<1, 1024>>>(cnt, off);
    cur_init_kernel<<<nb_nodes, NT>>>(off, cur);
    scatter_kernel<<<nb_edges, NT>>>(src, dst, cur, csr_src);

    // pack inputs + weights
    pack_x_kernel<<<nb_pack, NT>>>(x, Ah, Al);
    pack_w_kernel<<<nb_wpack, NT>>>(W1, B1h, B1l);
    pack_w_kernel<<<nb_wpack, NT>>>(W2, B2h, B2l);

    dim3 ggrid(4, MT);

    // Layer 1
    gemm_wmma_kernel<<<ggrid, 256, GEMM_SMEM_BYTES>>>(Ah, Al, B1h, B1l, bufA);
    gather_pack_kernel<<<N_NODES, 128>>>(bufA, off, csr_src, dis, b1, Ah, Al);

    // Layer 2
    gemm_wmma_kernel<<<ggrid, 256, GEMM_SMEM_BYTES>>>(Ah, Al, B2h, B2l, bufA);
    gather_heads_kernel<<<N_NODES, 128>>>(bufA, off, csr_src, dis, b2,
                                          Wo, bo, Ww, bw, out);
}

// round 6
// speedup vs baseline: 2.8897x; 1.1193x over previous
#include <cuda_runtime.h>
#include <cuda_bf16.h>
#include <mma.h>
#include <cstdint>

using namespace nvcuda;

#define N_NODES 25000
#define E_EDGES 200000
#define HID 512
#define MT 196
#define MPAD (MT * 128)        // 25088
#define SCAN_B 25              // ceil(25000/1024)

// ---------------------------------------------------------------------------
// Scratch (allocation-free: __device__ globals)
// ---------------------------------------------------------------------------
__device__ float g_bufA[MPAD * HID];            // hw (GEMM output)
__device__ float g_dis[N_NODES];
__device__ int   g_cnt[N_NODES];
__device__ int   g_off[N_NODES + 1];
__device__ int   g_cur[N_NODES];
__device__ int   g_part[SCAN_B];
__device__ int   g_boff[SCAN_B];
__device__ int   g_csr_src[E_EDGES];
__device__ __nv_bfloat16 g_Ah[MPAD * HID];
__device__ __nv_bfloat16 g_Al[MPAD * HID];
__device__ __nv_bfloat16 g_B1h[HID * HID];
__device__ __nv_bfloat16 g_B1l[HID * HID];
__device__ __nv_bfloat16 g_B2h[HID * HID];
__device__ __nv_bfloat16 g_B2l[HID * HID];

// ---------------------------------------------------------------------------
// CSR build (distributed scan)
// ---------------------------------------------------------------------------
__global__ void cnt_init_kernel(int* cnt) {
    int i = blockIdx.x * blockDim.x + threadIdx.x;
    if (i < N_NODES) cnt[i] = 0;
}
__global__ void cnt_count_kernel(const int* __restrict__ dst, int* cnt) {
    int e = blockIdx.x * blockDim.x + threadIdx.x;
    if (e < E_EDGES) atomicAdd(&cnt[dst[e]], 1);
}

// pass 1: per-block exclusive scan of 1024 cnt values -> off (block-local),
// block total -> part[b].  Also dis[i] = rsqrt(cnt+1).
__global__ __launch_bounds__(1024)
void scan_part_kernel(const int* __restrict__ cnt, int* __restrict__ off,
                      int* __restrict__ part, float* __restrict__ dis) {
    __shared__ int wsum[32];
    int b = blockIdx.x, t = threadIdx.x, lane = t & 31, warp = t >> 5;
    int idx = b * 1024 + t;
    int v = (idx < N_NODES) ? cnt[idx] : 0;
    if (idx < N_NODES) dis[idx] = rsqrtf((float)v + 1.0f);

    int incl = v;
    #pragma unroll
    for (int d = 1; d < 32; d <<= 1) {
        int u = __shfl_up_sync(0xffffffff, incl, d);
        if (lane >= d) incl += u;
    }
    if (lane == 31) wsum[warp] = incl;
    __syncthreads();
    if (warp == 0) {
        int w = wsum[lane];
        #pragma unroll
        for (int d = 1; d < 32; d <<= 1) {
            int u = __shfl_up_sync(0xffffffff, w, d);
            if (lane >= d) w += u;
        }
        wsum[lane] = w;
    }
    __syncthreads();
    int excl = incl - v + (warp ? wsum[warp - 1] : 0);
    if (idx < N_NODES) off[idx] = excl;
    if (t == 1023) part[b] = wsum[31];
}

// pass 2: single warp scans the 25 block totals
__global__ void scan_top_kernel(const int* __restrict__ part, int* __restrict__ boff,
                                int* __restrict__ off) {
    int lane = threadIdx.x;
    int v = (lane < SCAN_B) ? part[lane] : 0;
    int incl = v;
    #pragma unroll
    for (int d = 1; d < 32; d <<= 1) {
        int u = __shfl_up_sync(0xffffffff, incl, d);
        if (lane >= d) incl += u;
    }
    if (lane < SCAN_B) boff[lane] = incl - v;
    if (lane == 31) off[N_NODES] = incl;   // total = E
}

// pass 3: apply block offsets; also init cur
__global__ __launch_bounds__(1024)
void scan_apply_kernel(int* __restrict__ off, const int* __restrict__ boff,
                       int* __restrict__ cur) {
    int b = blockIdx.x, t = threadIdx.x;
    int idx = b * 1024 + t;
    if (idx < N_NODES) {
        int o = off[idx] + boff[b];
        off[idx] = o;
        cur[idx] = o;
    }
}

__global__ void scatter_kernel(const int* __restrict__ src, const int* __restrict__ dst,
                               int* cur, int* __restrict__ csr_src) {
    int e = blockIdx.x * blockDim.x + threadIdx.x;
    if (e >= E_EDGES) return;
    int pos = atomicAdd(&cur[dst[e]], 1);
    csr_src[pos] = src[e];
}

// ---------------------------------------------------------------------------
// Pack x -> bf16 hi/lo, zero-pads rows >= N_NODES
// ---------------------------------------------------------------------------
__global__ __launch_bounds__(256)
void pack_x_kernel(const float* __restrict__ src,
                   __nv_bfloat16* __restrict__ outH, __nv_bfloat16* __restrict__ outL) {
    int idx = blockIdx.x * blockDim.x + threadIdx.x;
    if (idx >= MPAD * 256) return;
    int m = idx >> 8;
    int k = (idx & 255) * 2;

    float v0 = 0.f, v1 = 0.f;
    if (m < N_NODES) {
        float2 v = *(const float2*)(src + (size_t)m * HID + k);
        v0 = v.x; v1 = v.y;
    }
    __nv_bfloat16 h0 = __float2bfloat16_rn(v0);
    __nv_bfloat16 h1 = __float2bfloat16_rn(v1);
    __nv_bfloat16 l0 = __float2bfloat16_rn(v0 - __bfloat162float(h0));
    __nv_bfloat16 l1 = __float2bfloat16_rn(v1 - __bfloat162float(h1));

    size_t off = (size_t)m * HID + k;
    *(__nv_bfloat162*)(outH + off) = __nv_bfloat162(h0, h1);
    *(__nv_bfloat162*)(outL + off) = __nv_bfloat162(l0, l1);
}

__global__ __launch_bounds__(256)
void pack_w_kernel(const float* __restrict__ W,
                   __nv_bfloat16* __restrict__ outH, __nv_bfloat16* __restrict__ outL) {
    int idx = blockIdx.x * blockDim.x + threadIdx.x;
    if (idx >= 512 * 256) return;
    int k = idx >> 8;
    int n = (idx & 255) * 2;

    float2 v = *(const float2*)(W + (size_t)k * HID + n);
    __nv_bfloat16 h0 = __float2bfloat16_rn(v.x);
    __nv_bfloat16 h1 = __float2bfloat16_rn(v.y);
    __nv_bfloat16 l0 = __float2bfloat16_rn(v.x - __bfloat162float(h0));
    __nv_bfloat16 l1 = __float2bfloat16_rn(v.y - __bfloat162float(h1));

    size_t off = (size_t)k * HID + n;
    *(__nv_bfloat162*)(outH + off) = __nv_bfloat162(h0, h1);
    *(__nv_bfloat162*)(outL + off) = __nv_bfloat162(l0, l1);
}

// ---------------------------------------------------------------------------
// cp.async helpers
// ---------------------------------------------------------------------------
__device__ __forceinline__ void cpa16(uint32_t dst, const void* src) {
    asm volatile("cp.async.cg.shared.global [%0], [%1], 16;" :: "r"(dst), "l"(src));
}
__device__ __forceinline__ void cpa_commit() {
    asm volatile("cp.async.commit_group;" ::: "memory");
}
__device__ __forceinline__ void cpa_wait0() {
    asm volatile("cp.async.wait_group 0;" ::: "memory");
}

// ---------------------------------------------------------------------------
// WMMA bf16-split GEMM, 2-stage cp.async pipeline, 2 CTAs/SM.
// ---------------------------------------------------------------------------
#define AS_STRIDE 40
#define BS_STRIDE 136
#define A_TILE_ELE (128 * AS_STRIDE)          // 5120
#define B_TILE_ELE (32 * BS_STRIDE)           // 4352
#define STAGE_ELE  (2 * A_TILE_ELE + 2 * B_TILE_ELE)   // 18944 bf16
#define GEMM_SMEM_BYTES (2 * STAGE_ELE * 2)            // 75776 B

__global__ __launch_bounds__(256, 2)
void gemm_wmma_kernel(const __nv_bfloat16* __restrict__ Ah, const __nv_bfloat16* __restrict__ Al,
                      const __nv_bfloat16* __restrict__ Bh, const __nv_bfloat16* __restrict__ Bl,
                      float* __restrict__ C) {
    extern __shared__ __nv_bfloat16 smem[];

    int tid = threadIdx.x;
    int bm = blockIdx.y * 128;
    int bn = blockIdx.x * 128;
    int wid = tid >> 5;
    int wm = (wid & 3) * 32;
    int wn = (wid >> 2) * 64;

    wmma::fragment<wmma::accumulator, 16, 16, 16, float> acc[2][4];
    #pragma unroll
    for (int i = 0; i < 2; i++)
        #pragma unroll
        for (int j = 0; j < 4; j++)
            wmma::fill_fragment(acc[i][j], 0.0f);

    int a_r0 = tid >> 2,  a_c0 = (tid & 3) * 8;
    int a_r1 = (tid + 256) >> 2, a_c1 = ((tid + 256) & 3) * 8;
    int b_r0 = tid >> 4,  b_c0 = (tid & 15) * 8;
    int b_r1 = (tid + 256) >> 4, b_c1 = ((tid + 256) & 15) * 8;

    uint32_t sbase = (uint32_t)__cvta_generic_to_shared(smem);

    auto load_stage = [&](int stage, int k0) {
        uint32_t st = sbase + (uint32_t)(stage * STAGE_ELE) * 2;
        uint32_t sAh = st;
        uint32_t sAl = st + A_TILE_ELE * 2;
        uint32_t sBh = st + 2 * A_TILE_ELE * 2;
        uint32_t sBl = st + (2 * A_TILE_ELE + B_TILE_ELE) * 2;

        const __nv_bfloat16* gA = Ah + (size_t)bm * HID + k0;
        const __nv_bfloat16* gAl2 = Al + (size_t)bm * HID + k0;
        const __nv_bfloat16* gB = Bh + (size_t)k0 * HID + bn;
        const __nv_bfloat16* gBl2 = Bl + (size_t)k0 * HID + bn;

        cpa16(sAh + (uint32_t)(a_r0 * AS_STRIDE + a_c0) * 2, gA  + (size_t)a_r0 * HID + a_c0);
        cpa16(sAh + (uint32_t)(a_r1 * AS_STRIDE + a_c1) * 2, gA  + (size_t)a_r1 * HID + a_c1);
        cpa16(sAl + (uint32_t)(a_r0 * AS_STRIDE + a_c0) * 2, gAl2 + (size_t)a_r0 * HID + a_c0);
        cpa16(sAl + (uint32_t)(a_r1 * AS_STRIDE + a_c1) * 2, gAl2 + (size_t)a_r1 * HID + a_c1);
        cpa16(sBh + (uint32_t)(b_r0 * BS_STRIDE + b_c0) * 2, gB  + (size_t)b_r0 * HID + b_c0);
        cpa16(sBh + (uint32_t)(b_r1 * BS_STRIDE + b_c1) * 2, gB  + (size_t)b_r1 * HID + b_c1);
        cpa16(sBl + (uint32_t)(b_r0 * BS_STRIDE + b_c0) * 2, gBl2 + (size_t)b_r0 * HID + b_c0);
        cpa16(sBl + (uint32_t)(b_r1 * BS_STRIDE + b_c1) * 2, gBl2 + (size_t)b_r1 * HID + b_c1);
        cpa_commit();
    };

    load_stage(0, 0);
    int buf = 0;

    for (int it = 0; it < 16; it++) {
        cpa_wait0();
        __syncthreads();   // orders: stage data visible AND prior compute finished
        if (it + 1 < 16) load_stage(buf ^ 1, (it + 1) * 32);

        __nv_bfloat16* st = smem + buf * STAGE_ELE;
        __nv_bfloat16* Ash = st;
        __nv_bfloat16* Asl = st + A_TILE_ELE;
        __nv_bfloat16* Bsh = st + 2 * A_TILE_ELE;
        __nv_bfloat16* Bsl = st + 2 * A_TILE_ELE + B_TILE_ELE;

        #pragma unroll
        for (int kk = 0; kk < 32; kk += 16) {
            wmma::fragment<wmma::matrix_a, 16, 16, 16, __nv_bfloat16, wmma::row_major> fa_h[2], fa_l[2];
            wmma::fragment<wmma::matrix_b, 16, 16, 16, __nv_bfloat16, wmma::row_major> fb_h[4], fb_l[4];
            #pragma unroll
            for (int i = 0; i < 2; i++) {
                wmma::load_matrix_sync(fa_h[i], Ash + (wm + i * 16) * AS_STRIDE + kk, AS_STRIDE);
                wmma::load_matrix_sync(fa_l[i], Asl + (wm + i * 16) * AS_STRIDE + kk, AS_STRIDE);
            }
            #pragma unroll
            for (int j = 0; j < 4; j++) {
                wmma::load_matrix_sync(fb_h[j], Bsh + kk * BS_STRIDE + wn + j * 16, BS_STRIDE);
                wmma::load_matrix_sync(fb_l[j], Bsl + kk * BS_STRIDE + wn + j * 16, BS_STRIDE);
            }
            #pragma unroll
            for (int i = 0; i < 2; i++)
                #pragma unroll
                for (int j = 0; j < 4; j++) {
                    wmma::mma_sync(acc[i][j], fa_h[i], fb_h[j], acc[i][j]);
                    wmma::mma_sync(acc[i][j], fa_l[i], fb_h[j], acc[i][j]);
                    wmma::mma_sync(acc[i][j], fa_h[i], fb_l[j], acc[i][j]);
                }
        }
        buf ^= 1;
    }

    #pragma unroll
    for (int i = 0; i < 2; i++)
        #pragma unroll
        for (int j = 0; j < 4; j++)
            wmma::store_matrix_sync(C + (size_t)(bm + wm + i * 16) * HID + bn + wn + j * 16,
                                    acc[i][j], HID, wmma::mem_row_major);
}

// ---------------------------------------------------------------------------
// Gather with smem-staged indices + unrolled MLP accumulate
// ---------------------------------------------------------------------------
#define GCH 32

__device__ __forceinline__ float4 gather_node(const float* __restrict__ hw,
                                              const int* __restrict__ off,
                                              const int* __restrict__ csr_src,
                                              const float* __restrict__ dis,
                                              int n, int t, float dn,
                                              int* s_idx, float* s_nrm) {
    const float4* hn = (const float4*)(hw + (size_t)n * HID);
    float4 v = hn[t];
    float dd = dn * dn;
    float4 acc = make_float4(v.x * dd, v.y * dd, v.z * dd, v.w * dd);

    int beg = __ldg(&off[n]), end = __ldg(&off[n + 1]);
    for (int base = beg; base < end; base += GCH) {
        int m = min(GCH, end - base);
        __syncthreads();
        if (t < m) {
            int s = __ldg(&csr_src[base + t]);
            s_idx[t] = s;
            s_nrm[t] = __ldg(&dis[s]) * dn;
        }
        __syncthreads();
        #pragma unroll 8
        for (int j = 0; j < m; j++) {
            int s = s_idx[j];
            float nrm = s_nrm[j];
            float4 h = ((const float4*)(hw + (size_t)s * HID))[t];
            acc.x = fmaf(h.x, nrm, acc.x);
            acc.y = fmaf(h.y, nrm, acc.y);
            acc.z = fmaf(h.z, nrm, acc.z);
            acc.w = fmaf(h.w, nrm, acc.w);
        }
    }
    return acc;
}

__global__ __launch_bounds__(128)
void gather_pack_kernel(const float* __restrict__ hw,
                        const int* __restrict__ off, const int* __restrict__ csr_src,
                        const float* __restrict__ dis, const float* __restrict__ bias,
                        __nv_bfloat16* __restrict__ outH, __nv_bfloat16* __restrict__ outL) {
    __shared__ int s_idx[GCH];
    __shared__ float s_nrm[GCH];
    int n = blockIdx.x;
    int t = threadIdx.x;
    float dn = __ldg(&dis[n]);

    float4 acc = gather_node(hw, off, csr_src, dis, n, t, dn, s_idx, s_nrm);

    int c = t * 4;
    float4 b = *(const float4*)(bias + c);
    float r0 = fmaxf(acc.x + b.x, 0.f);
    float r1 = fmaxf(acc.y + b.y, 0.f);
    float r2 = fmaxf(acc.z + b.z, 0.f);
    float r3 = fmaxf(acc.w + b.w, 0.f);

    __nv_bfloat16 h0 = __float2bfloat16_rn(r0), h1 = __float2bfloat16_rn(r1);
    __nv_bfloat16 h2 = __float2bfloat16_rn(r2), h3 = __float2bfloat16_rn(r3);
    __nv_bfloat16 l0 = __float2bfloat16_rn(r0 - __bfloat162float(h0));
    __nv_bfloat16 l1 = __float2bfloat16_rn(r1 - __bfloat162float(h1));
    __nv_bfloat16 l2 = __float2bfloat16_rn(r2 - __bfloat162float(h2));
    __nv_bfloat16 l3 = __float2bfloat16_rn(r3 - __bfloat162float(h3));

    size_t o = (size_t)n * HID + c;
    __nv_bfloat162 ph0(h0, h1), ph1(h2, h3), pl0(l0, l1), pl1(l2, l3);
    uint2 uh = make_uint2(*(uint32_t*)&ph0, *(uint32_t*)&ph1);
    uint2 ul = make_uint2(*(uint32_t*)&pl0, *(uint32_t*)&pl1);
    *(uint2*)(outH + o) = uh;
    *(uint2*)(outL + o) = ul;
}

__global__ __launch_bounds__(128)
void gather_heads_kernel(const float* __restrict__ hw,
                         const int* __restrict__ off, const int* __restrict__ csr_src,
                         const float* __restrict__ dis, const float* __restrict__ bias,
                         const float* __restrict__ Wo, const float* __restrict__ bo,
                         const float* __restrict__ Ww, const float* __restrict__ bw,
                         float* __restrict__ out) {
    __shared__ int s_idx[GCH];
    __shared__ float s_nrm[GCH];
    __shared__ float red[8];
    int n = blockIdx.x;
    int t = threadIdx.x;
    float dn = __ldg(&dis[n]);

    float4 acc = gather_node(hw, off, csr_src, dis, n, t, dn, s_idx, s_nrm);

    int c = t * 4;
    float4 b  = *(const float4*)(bias + c);
    float4 wo = *(const float4*)(Wo + c);
    float4 ww = *(const float4*)(Ww + c);
    float r0 = fmaxf(acc.x + b.x, 0.f);
    float r1 = fmaxf(acc.y + b.y, 0.f);
    float r2 = fmaxf(acc.z + b.z, 0.f);
    float r3 = fmaxf(acc.w + b.w, 0.f);

    float so = r0 * wo.x + r1 * wo.y + r2 * wo.z + r3 * wo.w;
    float sw = r0 * ww.x + r1 * ww.y + r2 * ww.z + r3 * ww.w;

    #pragma unroll
    for (int o2 = 16; o2; o2 >>= 1) {
        so += __shfl_down_sync(0xffffffff, so, o2);
        sw += __shfl_down_sync(0xffffffff, sw, o2);
    }
    int warp = t >> 5, lane = t & 31;
    if (lane == 0) { red[warp] = so; red[4 + warp] = sw; }
    __syncthreads();
    if (t == 0) {
        float fo = red[0] + red[1] + red[2] + red[3];
        float fw = red[4] + red[5] + red[6] + red[7];
        out[n]           = fo + bo[0];
        out[N_NODES + n] = fw + bw[0];
    }
}

// ---------------------------------------------------------------------------
// Launch
// ---------------------------------------------------------------------------
extern "C" void kernel_launch(void* const* d_in, const int* in_sizes, int n_in,
                              void* d_out, int out_size) {
    const float* x  = (const float*)d_in[0];
    const int*   ei = (const int*)d_in[1];
    const float* W1 = (const float*)d_in[2];
    const float* b1 = (const float*)d_in[3];
    const float* W2 = (const float*)d_in[4];
    const float* b2 = (const float*)d_in[5];
    const float* Wo = (const float*)d_in[6];
    const float* bo = (const float*)d_in[7];
    const float* Ww = (const float*)d_in[8];
    const float* bw = (const float*)d_in[9];

    const int* src = ei;
    const int* dst = ei + E_EDGES;
    float* out = (float*)d_out;

    float *bufA, *dis;
    int *cnt, *off, *cur, *part, *boff, *csr_src;
    __nv_bfloat16 *Ah, *Al, *B1h, *B1l, *B2h, *B2l;
    cudaGetSymbolAddress((void**)&bufA, g_bufA);
    cudaGetSymbolAddress((void**)&dis,  g_dis);
    cudaGetSymbolAddress((void**)&cnt,  g_cnt);
    cudaGetSymbolAddress((void**)&off,  g_off);
    cudaGetSymbolAddress((void**)&cur,  g_cur);
    cudaGetSymbolAddress((void**)&part, g_part);
    cudaGetSymbolAddress((void**)&boff, g_boff);
    cudaGetSymbolAddress((void**)&csr_src, g_csr_src);
    cudaGetSymbolAddress((void**)&Ah,   g_Ah);
    cudaGetSymbolAddress((void**)&Al,   g_Al);
    cudaGetSymbolAddress((void**)&B1h,  g_B1h);
    cudaGetSymbolAddress((void**)&B1l,  g_B1l);
    cudaGetSymbolAddress((void**)&B2h,  g_B2h);
    cudaGetSymbolAddress((void**)&B2l,  g_B2l);

    cudaFuncSetAttribute(gemm_wmma_kernel, cudaFuncAttributeMaxDynamicSharedMemorySize,
                         GEMM_SMEM_BYTES);

    const int NT = 256;
    int nb_nodes = (N_NODES + NT - 1) / NT;
    int nb_edges = (E_EDGES + NT - 1) / NT;
    int nb_pack  = (MPAD * 256 + NT - 1) / NT;
    int nb_wpack = (512 * 256 + NT - 1) / NT;

    // CSR + norms (distributed scan)
    cnt_init_kernel<<<nb_nodes, NT>>>(cnt);
    cnt_count_kernel<<<nb_edges, NT>>>(dst, cnt);
    scan_part_kernel<<<SCAN_B, 1024>>>(cnt, off, part, dis);
    scan_top_kernel<<<1, 32>>>(part, boff, off);
    scan_apply_kernel<<<SCAN_B, 1024>>>(off, boff, cur);
    scatter_kernel<<<nb_edges, NT>>>(src, dst, cur, csr_src);

    // pack inputs + weights
    pack_x_kernel<<<nb_pack, NT>>>(x, Ah, Al);
    pack_w_kernel<<<nb_wpack, NT>>>(W1, B1h, B1l);
    pack_w_kernel<<<nb_wpack, NT>>>(W2, B2h, B2l);

    dim3 ggrid(4, MT);

    // Layer 1
    gemm_wmma_kernel<<<ggrid, 256, GEMM_SMEM_BYTES>>>(Ah, Al, B1h, B1l, bufA);
    gather_pack_kernel<<<N_NODES, 128>>>(bufA, off, csr_src, dis, b1, Ah, Al);

    // Layer 2
    gemm_wmma_kernel<<<ggrid, 256, GEMM_SMEM_BYTES>>>(Ah, Al, B2h, B2l, bufA);
    gather_heads_kernel<<<N_NODES, 128>>>(bufA, off, csr_src, dis, b2,
                                          Wo, bo, Ww, bw, out);
}

// round 7
// speedup vs baseline: 2.9877x; 1.0339x over previous
#include <cuda_runtime.h>
#include <cuda_bf16.h>
#include <mma.h>
#include <cstdint>

using namespace nvcuda;

#define N_NODES 25000
#define E_EDGES 200000
#define HID 512
#define MT 196
#define MPAD (MT * 128)        // 25088
#define SCAN_B 25              // ceil(25000/1024)

// ---------------------------------------------------------------------------
// Scratch (allocation-free: __device__ globals)
// ---------------------------------------------------------------------------
__device__ float g_bufA[MPAD * HID];            // hw (GEMM output)
__device__ float g_dis[N_NODES];
__device__ int   g_cnt[N_NODES];
__device__ int   g_off[N_NODES + 1];
__device__ int   g_cur[N_NODES];
__device__ int   g_part[SCAN_B];
__device__ int   g_boff[SCAN_B];
__device__ int   g_csr_src[E_EDGES];
__device__ __nv_bfloat16 g_Ah[MPAD * HID];
__device__ __nv_bfloat16 g_Al[MPAD * HID];
__device__ __nv_bfloat16 g_B1h[HID * HID];
__device__ __nv_bfloat16 g_B1l[HID * HID];
__device__ __nv_bfloat16 g_B2h[HID * HID];
__device__ __nv_bfloat16 g_B2l[HID * HID];

// ---------------------------------------------------------------------------
// CSR build (distributed scan)
// ---------------------------------------------------------------------------
__global__ void cnt_count_kernel(const int* __restrict__ dst, int* cnt) {
    int e = blockIdx.x * blockDim.x + threadIdx.x;
    if (e < E_EDGES) atomicAdd(&cnt[dst[e]], 1);
}

__global__ __launch_bounds__(1024)
void scan_part_kernel(const int* __restrict__ cnt, int* __restrict__ off,
                      int* __restrict__ part, float* __restrict__ dis) {
    __shared__ int wsum[32];
    int b = blockIdx.x, t = threadIdx.x, lane = t & 31, warp = t >> 5;
    int idx = b * 1024 + t;
    int v = (idx < N_NODES) ? cnt[idx] : 0;
    if (idx < N_NODES) dis[idx] = rsqrtf((float)v + 1.0f);

    int incl = v;
    #pragma unroll
    for (int d = 1; d < 32; d <<= 1) {
        int u = __shfl_up_sync(0xffffffff, incl, d);
        if (lane >= d) incl += u;
    }
    if (lane == 31) wsum[warp] = incl;
    __syncthreads();
    if (warp == 0) {
        int w = wsum[lane];
        #pragma unroll
        for (int d = 1; d < 32; d <<= 1) {
            int u = __shfl_up_sync(0xffffffff, w, d);
            if (lane >= d) w += u;
        }
        wsum[lane] = w;
    }
    __syncthreads();
    int excl = incl - v + (warp ? wsum[warp - 1] : 0);
    if (idx < N_NODES) off[idx] = excl;
    if (t == 1023) part[b] = wsum[31];
}

__global__ void scan_top_kernel(const int* __restrict__ part, int* __restrict__ boff,
                                int* __restrict__ off) {
    int lane = threadIdx.x;
    int v = (lane < SCAN_B) ? part[lane] : 0;
    int incl = v;
    #pragma unroll
    for (int d = 1; d < 32; d <<= 1) {
        int u = __shfl_up_sync(0xffffffff, incl, d);
        if (lane >= d) incl += u;
    }
    if (lane < SCAN_B) boff[lane] = incl - v;
    if (lane == 31) off[N_NODES] = incl;
}

__global__ __launch_bounds__(1024)
void scan_apply_kernel(int* __restrict__ off, const int* __restrict__ boff,
                       int* __restrict__ cur) {
    int b = blockIdx.x, t = threadIdx.x;
    int idx = b * 1024 + t;
    if (idx < N_NODES) {
        int o = off[idx] + boff[b];
        off[idx] = o;
        cur[idx] = o;
    }
}

__global__ void scatter_kernel(const int* __restrict__ src, const int* __restrict__ dst,
                               int* cur, int* __restrict__ csr_src) {
    int e = blockIdx.x * blockDim.x + threadIdx.x;
    if (e >= E_EDGES) return;
    int pos = atomicAdd(&cur[dst[e]], 1);
    csr_src[pos] = src[e];
}

// ---------------------------------------------------------------------------
// Pack x -> bf16 hi/lo, zero-pads rows >= N_NODES
// ---------------------------------------------------------------------------
__global__ __launch_bounds__(256)
void pack_x_kernel(const float* __restrict__ src,
                   __nv_bfloat16* __restrict__ outH, __nv_bfloat16* __restrict__ outL) {
    int idx = blockIdx.x * blockDim.x + threadIdx.x;
    if (idx >= MPAD * 256) return;
    int m = idx >> 8;
    int k = (idx & 255) * 2;

    float v0 = 0.f, v1 = 0.f;
    if (m < N_NODES) {
        float2 v = *(const float2*)(src + (size_t)m * HID + k);
        v0 = v.x; v1 = v.y;
    }
    __nv_bfloat16 h0 = __float2bfloat16_rn(v0);
    __nv_bfloat16 h1 = __float2bfloat16_rn(v1);
    __nv_bfloat16 l0 = __float2bfloat16_rn(v0 - __bfloat162float(h0));
    __nv_bfloat16 l1 = __float2bfloat16_rn(v1 - __bfloat162float(h1));

    size_t off = (size_t)m * HID + k;
    *(__nv_bfloat162*)(outH + off) = __nv_bfloat162(h0, h1);
    *(__nv_bfloat162*)(outL + off) = __nv_bfloat162(l0, l1);
}

__global__ __launch_bounds__(256)
void pack_w_kernel(const float* __restrict__ W,
                   __nv_bfloat16* __restrict__ outH, __nv_bfloat16* __restrict__ outL) {
    int idx = blockIdx.x * blockDim.x + threadIdx.x;
    if (idx >= 512 * 256) return;
    int k = idx >> 8;
    int n = (idx & 255) * 2;

    float2 v = *(const float2*)(W + (size_t)k * HID + n);
    __nv_bfloat16 h0 = __float2bfloat16_rn(v.x);
    __nv_bfloat16 h1 = __float2bfloat16_rn(v.y);
    __nv_bfloat16 l0 = __float2bfloat16_rn(v.x - __bfloat162float(h0));
    __nv_bfloat16 l1 = __float2bfloat16_rn(v.y - __bfloat162float(h1));

    size_t off = (size_t)k * HID + n;
    *(__nv_bfloat162*)(outH + off) = __nv_bfloat162(h0, h1);
    *(__nv_bfloat162*)(outL + off) = __nv_bfloat162(l0, l1);
}

// ---------------------------------------------------------------------------
// cp.async helpers
// ---------------------------------------------------------------------------
__device__ __forceinline__ void cpa16(uint32_t dst, const void* src) {
    asm volatile("cp.async.cg.shared.global [%0], [%1], 16;" :: "r"(dst), "l"(src));
}
__device__ __forceinline__ void cpa_commit() {
    asm volatile("cp.async.commit_group;" ::: "memory");
}
__device__ __forceinline__ void cpa_wait0() {
    asm volatile("cp.async.wait_group 0;" ::: "memory");
}

// ---------------------------------------------------------------------------
// WMMA bf16-split GEMM, 2-stage cp.async pipeline, 2 CTAs/SM.
// ---------------------------------------------------------------------------
#define AS_STRIDE 40
#define BS_STRIDE 136
#define A_TILE_ELE (128 * AS_STRIDE)
#define B_TILE_ELE (32 * BS_STRIDE)
#define STAGE_ELE  (2 * A_TILE_ELE + 2 * B_TILE_ELE)
#define GEMM_SMEM_BYTES (2 * STAGE_ELE * 2)

__global__ __launch_bounds__(256, 2)
void gemm_wmma_kernel(const __nv_bfloat16* __restrict__ Ah, const __nv_bfloat16* __restrict__ Al,
                      const __nv_bfloat16* __restrict__ Bh, const __nv_bfloat16* __restrict__ Bl,
                      float* __restrict__ C) {
    extern __shared__ __nv_bfloat16 smem[];

    int tid = threadIdx.x;
    int bm = blockIdx.y * 128;
    int bn = blockIdx.x * 128;
    int wid = tid >> 5;
    int wm = (wid & 3) * 32;
    int wn = (wid >> 2) * 64;

    wmma::fragment<wmma::accumulator, 16, 16, 16, float> acc[2][4];
    #pragma unroll
    for (int i = 0; i < 2; i++)
        #pragma unroll
        for (int j = 0; j < 4; j++)
            wmma::fill_fragment(acc[i][j], 0.0f);

    int a_r0 = tid >> 2,  a_c0 = (tid & 3) * 8;
    int a_r1 = (tid + 256) >> 2, a_c1 = ((tid + 256) & 3) * 8;
    int b_r0 = tid >> 4,  b_c0 = (tid & 15) * 8;
    int b_r1 = (tid + 256) >> 4, b_c1 = ((tid + 256) & 15) * 8;

    uint32_t sbase = (uint32_t)__cvta_generic_to_shared(smem);

    auto load_stage = [&](int stage, int k0) {
        uint32_t st = sbase + (uint32_t)(stage * STAGE_ELE) * 2;
        uint32_t sAh = st;
        uint32_t sAl = st + A_TILE_ELE * 2;
        uint32_t sBh = st + 2 * A_TILE_ELE * 2;
        uint32_t sBl = st + (2 * A_TILE_ELE + B_TILE_ELE) * 2;

        const __nv_bfloat16* gA = Ah + (size_t)bm * HID + k0;
        const __nv_bfloat16* gAl2 = Al + (size_t)bm * HID + k0;
        const __nv_bfloat16* gB = Bh + (size_t)k0 * HID + bn;
        const __nv_bfloat16* gBl2 = Bl + (size_t)k0 * HID + bn;

        cpa16(sAh + (uint32_t)(a_r0 * AS_STRIDE + a_c0) * 2, gA  + (size_t)a_r0 * HID + a_c0);
        cpa16(sAh + (uint32_t)(a_r1 * AS_STRIDE + a_c1) * 2, gA  + (size_t)a_r1 * HID + a_c1);
        cpa16(sAl + (uint32_t)(a_r0 * AS_STRIDE + a_c0) * 2, gAl2 + (size_t)a_r0 * HID + a_c0);
        cpa16(sAl + (uint32_t)(a_r1 * AS_STRIDE + a_c1) * 2, gAl2 + (size_t)a_r1 * HID + a_c1);
        cpa16(sBh + (uint32_t)(b_r0 * BS_STRIDE + b_c0) * 2, gB  + (size_t)b_r0 * HID + b_c0);
        cpa16(sBh + (uint32_t)(b_r1 * BS_STRIDE + b_c1) * 2, gB  + (size_t)b_r1 * HID + b_c1);
        cpa16(sBl + (uint32_t)(b_r0 * BS_STRIDE + b_c0) * 2, gBl2 + (size_t)b_r0 * HID + b_c0);
        cpa16(sBl + (uint32_t)(b_r1 * BS_STRIDE + b_c1) * 2, gBl2 + (size_t)b_r1 * HID + b_c1);
        cpa_commit();
    };

    load_stage(0, 0);
    int buf = 0;

    for (int it = 0; it < 16; it++) {
        cpa_wait0();
        __syncthreads();
        if (it + 1 < 16) load_stage(buf ^ 1, (it + 1) * 32);

        __nv_bfloat16* st = smem + buf * STAGE_ELE;
        __nv_bfloat16* Ash = st;
        __nv_bfloat16* Asl = st + A_TILE_ELE;
        __nv_bfloat16* Bsh = st + 2 * A_TILE_ELE;
        __nv_bfloat16* Bsl = st + 2 * A_TILE_ELE + B_TILE_ELE;

        #pragma unroll
        for (int kk = 0; kk < 32; kk += 16) {
            wmma::fragment<wmma::matrix_a, 16, 16, 16, __nv_bfloat16, wmma::row_major> fa_h[2], fa_l[2];
            wmma::fragment<wmma::matrix_b, 16, 16, 16, __nv_bfloat16, wmma::row_major> fb_h[4], fb_l[4];
            #pragma unroll
            for (int i = 0; i < 2; i++) {
                wmma::load_matrix_sync(fa_h[i], Ash + (wm + i * 16) * AS_STRIDE + kk, AS_STRIDE);
                wmma::load_matrix_sync(fa_l[i], Asl + (wm + i * 16) * AS_STRIDE + kk, AS_STRIDE);
            }
            #pragma unroll
            for (int j = 0; j < 4; j++) {
                wmma::load_matrix_sync(fb_h[j], Bsh + kk * BS_STRIDE + wn + j * 16, BS_STRIDE);
                wmma::load_matrix_sync(fb_l[j], Bsl + kk * BS_STRIDE + wn + j * 16, BS_STRIDE);
            }
            #pragma unroll
            for (int i = 0; i < 2; i++)
                #pragma unroll
                for (int j = 0; j < 4; j++) {
                    wmma::mma_sync(acc[i][j], fa_h[i], fb_h[j], acc[i][j]);
                    wmma::mma_sync(acc[i][j], fa_l[i], fb_h[j], acc[i][j]);
                    wmma::mma_sync(acc[i][j], fa_h[i], fb_l[j], acc[i][j]);
                }
        }
        buf ^= 1;
    }

    #pragma unroll
    for (int i = 0; i < 2; i++)
        #pragma unroll
        for (int j = 0; j < 4; j++)
            wmma::store_matrix_sync(C + (size_t)(bm + wm + i * 16) * HID + bn + wn + j * 16,
                                    acc[i][j], HID, wmma::mem_row_major);
}

// ---------------------------------------------------------------------------
// Gather with smem-staged indices + unrolled MLP accumulate
// ---------------------------------------------------------------------------
#define GCH 32

__device__ __forceinline__ float4 gather_node(const float* __restrict__ hw,
                                              const int* __restrict__ off,
                                              const int* __restrict__ csr_src,
                                              const float* __restrict__ dis,
                                              int n, int t, float dn,
                                              int* s_idx, float* s_nrm) {
    const float4* hn = (const float4*)(hw + (size_t)n * HID);
    float4 v = hn[t];
    float dd = dn * dn;
    float4 acc = make_float4(v.x * dd, v.y * dd, v.z * dd, v.w * dd);

    int beg = __ldg(&off[n]), end = __ldg(&off[n + 1]);
    for (int base = beg; base < end; base += GCH) {
        int m = min(GCH, end - base);
        __syncthreads();
        if (t < m) {
            int s = __ldg(&csr_src[base + t]);
            s_idx[t] = s;
            s_nrm[t] = __ldg(&dis[s]) * dn;
        }
        __syncthreads();
        #pragma unroll 8
        for (int j = 0; j < m; j++) {
            int s = s_idx[j];
            float nrm = s_nrm[j];
            float4 h = ((const float4*)(hw + (size_t)s * HID))[t];
            acc.x = fmaf(h.x, nrm, acc.x);
            acc.y = fmaf(h.y, nrm, acc.y);
            acc.z = fmaf(h.z, nrm, acc.z);
            acc.w = fmaf(h.w, nrm, acc.w);
        }
    }
    return acc;
}

__global__ __launch_bounds__(128)
void gather_pack_kernel(const float* __restrict__ hw,
                        const int* __restrict__ off, const int* __restrict__ csr_src,
                        const float* __restrict__ dis, const float* __restrict__ bias,
                        __nv_bfloat16* __restrict__ outH, __nv_bfloat16* __restrict__ outL) {
    __shared__ int s_idx[GCH];
    __shared__ float s_nrm[GCH];
    int n = blockIdx.x;
    int t = threadIdx.x;
    float dn = __ldg(&dis[n]);

    float4 acc = gather_node(hw, off, csr_src, dis, n, t, dn, s_idx, s_nrm);

    int c = t * 4;
    float4 b = *(const float4*)(bias + c);
    float r0 = fmaxf(acc.x + b.x, 0.f);
    float r1 = fmaxf(acc.y + b.y, 0.f);
    float r2 = fmaxf(acc.z + b.z, 0.f);
    float r3 = fmaxf(acc.w + b.w, 0.f);

    __nv_bfloat16 h0 = __float2bfloat16_rn(r0), h1 = __float2bfloat16_rn(r1);
    __nv_bfloat16 h2 = __float2bfloat16_rn(r2), h3 = __float2bfloat16_rn(r3);
    __nv_bfloat16 l0 = __float2bfloat16_rn(r0 - __bfloat162float(h0));
    __nv_bfloat16 l1 = __float2bfloat16_rn(r1 - __bfloat162float(h1));
    __nv_bfloat16 l2 = __float2bfloat16_rn(r2 - __bfloat162float(h2));
    __nv_bfloat16 l3 = __float2bfloat16_rn(r3 - __bfloat162float(h3));

    size_t o = (size_t)n * HID + c;
    __nv_bfloat162 ph0(h0, h1), ph1(h2, h3), pl0(l0, l1), pl1(l2, l3);
    uint2 uh = make_uint2(*(uint32_t*)&ph0, *(uint32_t*)&ph1);
    uint2 ul = make_uint2(*(uint32_t*)&pl0, *(uint32_t*)&pl1);
    *(uint2*)(outH + o) = uh;
    *(uint2*)(outL + o) = ul;
}

__global__ __launch_bounds__(128)
void gather_heads_kernel(const float* __restrict__ hw,
                         const int* __restrict__ off, const int* __restrict__ csr_src,
                         const float* __restrict__ dis, const float* __restrict__ bias,
                         const float* __restrict__ Wo, const float* __restrict__ bo,
                         const float* __restrict__ Ww, const float* __restrict__ bw,
                         float* __restrict__ out) {
    __shared__ int s_idx[GCH];
    __shared__ float s_nrm[GCH];
    __shared__ float red[8];
    int n = blockIdx.x;
    int t = threadIdx.x;
    float dn = __ldg(&dis[n]);

    float4 acc = gather_node(hw, off, csr_src, dis, n, t, dn, s_idx, s_nrm);

    int c = t * 4;
    float4 b  = *(const float4*)(bias + c);
    float4 wo = *(const float4*)(Wo + c);
    float4 ww = *(const float4*)(Ww + c);
    float r0 = fmaxf(acc.x + b.x, 0.f);
    float r1 = fmaxf(acc.y + b.y, 0.f);
    float r2 = fmaxf(acc.z + b.z, 0.f);
    float r3 = fmaxf(acc.w + b.w, 0.f);

    float so = r0 * wo.x + r1 * wo.y + r2 * wo.z + r3 * wo.w;
    float sw = r0 * ww.x + r1 * ww.y + r2 * ww.z + r3 * ww.w;

    #pragma unroll
    for (int o2 = 16; o2; o2 >>= 1) {
        so += __shfl_down_sync(0xffffffff, so, o2);
        sw += __shfl_down_sync(0xffffffff, sw, o2);
    }
    int warp = t >> 5, lane = t & 31;
    if (lane == 0) { red[warp] = so; red[4 + warp] = sw; }
    __syncthreads();
    if (t == 0) {
        float fo = red[0] + red[1] + red[2] + red[3];
        float fw = red[4] + red[5] + red[6] + red[7];
        out[n]           = fo + bo[0];
        out[N_NODES + n] = fw + bw[0];
    }
}

// ---------------------------------------------------------------------------
// Launch — two-stream overlap: CSR chain + pack_w2 run concurrently with
// pack_x + pack_w1 + GEMM1; joined before gather_pack.
// ---------------------------------------------------------------------------
extern "C" void kernel_launch(void* const* d_in, const int* in_sizes, int n_in,
                              void* d_out, int out_size) {
    const float* x  = (const float*)d_in[0];
    const int*   ei = (const int*)d_in[1];
    const float* W1 = (const float*)d_in[2];
    const float* b1 = (const float*)d_in[3];
    const float* W2 = (const float*)d_in[4];
    const float* b2 = (const float*)d_in[5];
    const float* Wo = (const float*)d_in[6];
    const float* bo = (const float*)d_in[7];
    const float* Ww = (const float*)d_in[8];
    const float* bw = (const float*)d_in[9];

    const int* src = ei;
    const int* dst = ei + E_EDGES;
    float* out = (float*)d_out;

    float *bufA, *dis;
    int *cnt, *off, *cur, *part, *boff, *csr_src;
    __nv_bfloat16 *Ah, *Al, *B1h, *B1l, *B2h, *B2l;
    cudaGetSymbolAddress((void**)&bufA, g_bufA);
    cudaGetSymbolAddress((void**)&dis,  g_dis);
    cudaGetSymbolAddress((void**)&cnt,  g_cnt);
    cudaGetSymbolAddress((void**)&off,  g_off);
    cudaGetSymbolAddress((void**)&cur,  g_cur);
    cudaGetSymbolAddress((void**)&part, g_part);
    cudaGetSymbolAddress((void**)&boff, g_boff);
    cudaGetSymbolAddress((void**)&csr_src, g_csr_src);
    cudaGetSymbolAddress((void**)&Ah,   g_Ah);
    cudaGetSymbolAddress((void**)&Al,   g_Al);
    cudaGetSymbolAddress((void**)&B1h,  g_B1h);
    cudaGetSymbolAddress((void**)&B1l,  g_B1l);
    cudaGetSymbolAddress((void**)&B2h,  g_B2h);
    cudaGetSymbolAddress((void**)&B2l,  g_B2l);

    cudaFuncSetAttribute(gemm_wmma_kernel, cudaFuncAttributeMaxDynamicSharedMemorySize,
                         GEMM_SMEM_BYTES);

    // side stream + fork/join events (created per call; kernel_launch runs
    // only for the correctness pass and the single capture pass)
    cudaStream_t s1;
    cudaEvent_t evFork, evJoin;
    cudaStreamCreateWithFlags(&s1, cudaStreamNonBlocking);
    cudaEventCreateWithFlags(&evFork, cudaEventDisableTiming);
    cudaEventCreateWithFlags(&evJoin, cudaEventDisableTiming);

    const int NT = 256;
    int nb_edges = (E_EDGES + NT - 1) / NT;
    int nb_pack  = (MPAD * 256 + NT - 1) / NT;
    int nb_wpack = (512 * 256 + NT - 1) / NT;

    // fork
    cudaEventRecord(evFork, 0);
    cudaStreamWaitEvent(s1, evFork, 0);

    // --- side stream: CSR build + pack_w2 ---
    cudaMemsetAsync(cnt, 0, N_NODES * sizeof(int), s1);
    cnt_count_kernel<<<nb_edges, NT, 0, s1>>>(dst, cnt);
    scan_part_kernel<<<SCAN_B, 1024, 0, s1>>>(cnt, off, part, dis);
    scan_top_kernel<<<1, 32, 0, s1>>>(part, boff, off);
    scan_apply_kernel<<<SCAN_B, 1024, 0, s1>>>(off, boff, cur);
    scatter_kernel<<<nb_edges, NT, 0, s1>>>(src, dst, cur, csr_src);
    pack_w_kernel<<<nb_wpack, NT, 0, s1>>>(W2, B2h, B2l);
    cudaEventRecord(evJoin, s1);

    // --- main stream: pack + GEMM1 ---
    pack_x_kernel<<<nb_pack, NT>>>(x, Ah, Al);
    pack_w_kernel<<<nb_wpack, NT>>>(W1, B1h, B1l);

    dim3 ggrid(4, MT);
    gemm_wmma_kernel<<<ggrid, 256, GEMM_SMEM_BYTES>>>(Ah, Al, B1h, B1l, bufA);

    // join: gather needs CSR (off/csr_src/dis)
    cudaStreamWaitEvent(0, evJoin, 0);

    gather_pack_kernel<<<N_NODES, 128>>>(bufA, off, csr_src, dis, b1, Ah, Al);
    gemm_wmma_kernel<<<ggrid, 256, GEMM_SMEM_BYTES>>>(Ah, Al, B2h, B2l, bufA);
    gather_heads_kernel<<<N_NODES, 128>>>(bufA, off, csr_src, dis, b2,
                                          Wo, bo, Ww, bw, out);
}